// round 13
// baseline (speedup 1.0000x reference)
#include <cuda_runtime.h>
#include <cuda_fp16.h>
#include <math.h>
#include <stdint.h>

// Dims
constexpr int DS  = 256;   // S
constexpr int DN  = 768;   // N
constexpr int DCM = 64;    // CM
constexpr int DCZ = 128;   // CZ
constexpr int DH  = 8;     // heads
constexpr int DCH = 32;    // per-head channels
constexpr int DHC = 256;   // H*CH
constexpr int DSN = DS * DN;          // 196608 rows of m
constexpr int DNN = DN * DN;          // 589824 pairs
constexpr int DCOL = DS * DCH;        // 8192 GEMM cols

// Scratch (device globals; no allocations allowed)
__device__ __half d_vt[(size_t)DH * DCOL * DN];  // v^T fp16: [h][n=s*32+d][j]
__device__ __half d_bh[(size_t)DH * DNN];        // softmax probs fp16: [h][i][j]
__device__ __half d_gh[(size_t)DSN * DHC];       // gate fp16: [s*N+j][hc]
__device__ float  d_b[(size_t)DH * DNN];         // logits f32 (K2 -> K3)
__device__ __half d_oh[(size_t)DH * DN * DCOL];  // o fp16: [h][i][s*32+d]
__device__ __half d_wmh[DHC * DCM];              // Wm fp16
__device__ __half d_wgh[DHC * DCM];              // Wg fp16
__device__ __half d_woh[DCM * DHC];              // Wo fp16

__device__ __forceinline__ uint32_t smem_u32(const void* p) {
    uint32_t a;
    asm("{ .reg .u64 t; cvta.to.shared.u64 t, %1; cvt.u32.u64 %0, t; }"
        : "=r"(a) : "l"(p));
    return a;
}

#define MMA_F16(acc, af, bf)                                                  \
    asm volatile(                                                             \
        "mma.sync.aligned.m16n8k16.row.col.f32.f16.f16.f32 "                  \
        "{%0,%1,%2,%3}, {%4,%5,%6,%7}, {%8,%9}, {%0,%1,%2,%3};"               \
        : "+f"((acc)[0]), "+f"((acc)[1]), "+f"((acc)[2]), "+f"((acc)[3])      \
        : "r"((af)[0]), "r"((af)[1]), "r"((af)[2]), "r"((af)[3]),             \
          "r"((bf)[0]), "r"((bf)[1]))

#define LDSM_X4(r0, r1, r2, r3, addr)                                         \
    asm volatile("ldmatrix.sync.aligned.m8n8.x4.shared.b16 {%0,%1,%2,%3}, [%4];" \
        : "=r"(r0), "=r"(r1), "=r"(r2), "=r"(r3) : "r"(addr))

constexpr int STG = 136;   // staged-epilogue stride (halfs): 272 B, 16B-aligned rows

// ---------------------------------------------------------------------------
// K0: one-time weight conversion f32 -> fp16 (Wm, Wg, Wo). Grid 64 x 256.
// ---------------------------------------------------------------------------
__global__ void k0_convert_w(const float* __restrict__ Wm,
                             const float* __restrict__ Wg,
                             const float* __restrict__ Wo) {
    int idx = blockIdx.x * 256 + threadIdx.x;   // 0..16383
    d_wmh[idx] = __float2half_rn(Wm[idx]);
    d_wgh[idx] = __float2half_rn(Wg[idx]);
    d_woh[idx] = __float2half_rn(Wo[idx]);
}

// ---------------------------------------------------------------------------
// K1 v4 (fp16 mma, register LN, pre-converted weights, half-stage epilogue).
// smem: mh[128][72] + Wh[128][72] + stage[64][136] = 54272 B -> 4 CTAs/SM.
// ---------------------------------------------------------------------------
constexpr int K1MH = 72;
constexpr int K1_SMEM = (128 * K1MH + 128 * K1MH + 64 * STG) * 2;  // 54272

__global__ void __launch_bounds__(256) k1_ln_vg_v4(const float* __restrict__ m,
                                                   const float* __restrict__ nw,
                                                   const float* __restrict__ nb) {
    extern __shared__ __half sm1h[];
    __half* mh    = sm1h;                   // [128][72]
    __half* Wh    = sm1h + 128 * K1MH;      // [128][72]
    __half* stage = sm1h + 256 * K1MH;      // [64][136]

    const int tid = threadIdx.x;
    const int gr0 = blockIdx.x * 128;

    // LN in registers: 2 threads per row, 32 channels each, 1 shuffle combine
    {
        const int row = tid >> 1;
        const int hf  = tid & 1;
        const float* src = m + (size_t)(gr0 + row) * DCM + hf * 32;
        float4 x[8];
        #pragma unroll
        for (int t = 0; t < 8; t++) x[t] = *(const float4*)&src[t * 4];
        float s1 = 0.f, s2 = 0.f;
        #pragma unroll
        for (int t = 0; t < 8; t++) {
            s1 += x[t].x + x[t].y + x[t].z + x[t].w;
            s2 += x[t].x * x[t].x + x[t].y * x[t].y + x[t].z * x[t].z + x[t].w * x[t].w;
        }
        s1 += __shfl_xor_sync(0xffffffffu, s1, 1);
        s2 += __shfl_xor_sync(0xffffffffu, s2, 1);
        float mu  = s1 * (1.f / 64.f);
        float inv = rsqrtf(s2 * (1.f / 64.f) - mu * mu + 1e-5f);
        const float* xp = (const float*)x;
        #pragma unroll
        for (int k = 0; k < 32; k += 2) {
            int ch = hf * 32 + k;
            float v0 = (xp[k]     - mu) * inv * nw[ch]     + nb[ch];
            float v1 = (xp[k + 1] - mu) * inv * nw[ch + 1] + nb[ch + 1];
            *(__half2*)&mh[row * K1MH + ch] = __floats2half2_rn(v0, v1);
        }
    }
    __syncthreads();

    const int lane = tid & 31;
    const int wid  = tid >> 5;
    const int warp_m = wid >> 2;   // 0..1
    const int warp_n = wid & 3;    // 0..3
    const int gid = lane >> 2;
    const int tq  = lane & 3;

    const uint32_t mh_base = smem_u32(mh);
    const uint32_t wh_base = smem_u32(Wh);
    const uint32_t a_lane = (uint32_t)((warp_m * 64 + (lane & 15)) * 144 + (lane >> 4) * 16);
    const uint32_t b_lane = (uint32_t)((warp_n * 32 + (lane & 7) + ((lane >> 4) & 1) * 8) * 144
                                       + ((lane >> 3) & 1) * 16);

    const int ss = gr0 / DN;
    const int jj0 = gr0 - ss * DN;   // 768 % 128 == 0: no straddle

    for (int c4 = 0; c4 < 4; c4++) {
        const bool vp = (c4 < 2);
        const __half* Wsrc = vp ? (d_wmh + (size_t)(c4 * 128) * DCM)
                                : (d_wgh + (size_t)((c4 - 2) * 128) * DCM);
        // stage Wh[n][k] via uint4 copies
        #pragma unroll
        for (int t = 0; t < 4; t++) {
            int idx = tid + t * 256;          // 0..1023
            int n = idx >> 3, c8 = (idx & 7) * 8;
            *(uint4*)&Wh[n * K1MH + c8] = *(const uint4*)&Wsrc[n * DCM + c8];
        }
        __syncthreads();

        const uint32_t a_base = vp ? wh_base : mh_base;
        const uint32_t b_base = vp ? mh_base : wh_base;

        float acc[4][4][4];
        #pragma unroll
        for (int i = 0; i < 4; i++)
            #pragma unroll
            for (int j = 0; j < 4; j++)
                #pragma unroll
                for (int r = 0; r < 4; r++) acc[i][j][r] = 0.f;

        #pragma unroll
        for (int k16 = 0; k16 < 4; k16++) {
            uint32_t af[4][4], bf[4][2];
            #pragma unroll
            for (int mt = 0; mt < 4; mt++) {
                uint32_t addr = a_base + a_lane + (uint32_t)(mt * 16 * 144 + k16 * 32);
                LDSM_X4(af[mt][0], af[mt][1], af[mt][2], af[mt][3], addr);
            }
            #pragma unroll
            for (int ntp = 0; ntp < 2; ntp++) {
                uint32_t addr = b_base + b_lane + (uint32_t)(ntp * 16 * 144 + k16 * 32);
                LDSM_X4(bf[2 * ntp][0], bf[2 * ntp][1], bf[2 * ntp + 1][0], bf[2 * ntp + 1][1], addr);
            }
            #pragma unroll
            for (int mt = 0; mt < 4; mt++)
                #pragma unroll
                for (int nt = 0; nt < 4; nt++)
                    MMA_F16(acc[mt][nt], af[mt], bf[nt]);
        }

        // epilogue in two 64-row passes (stage is [64][136])
        #pragma unroll
        for (int p = 0; p < 2; p++) {
            if (warp_m == p) {
                #pragma unroll
                for (int mt = 0; mt < 4; mt++) {
                    #pragma unroll
                    for (int half = 0; half < 2; half++) {
                        int rloc = mt * 16 + gid + half * 8;   // 0..63 within pass
                        #pragma unroll
                        for (int nt = 0; nt < 4; nt++) {
                            int cloc = warp_n * 32 + nt * 8 + tq * 2;
                            float c0 = acc[mt][nt][half * 2];
                            float c1 = acc[mt][nt][half * 2 + 1];
                            if (!vp) {
                                c0 = 1.f / (1.f + __expf(-c0));
                                c1 = 1.f / (1.f + __expf(-c1));
                            }
                            *(__half2*)&stage[rloc * STG + cloc] = __floats2half2_rn(c0, c1);
                        }
                    }
                }
            }
            __syncthreads();

            #pragma unroll
            for (int t = 0; t < 4; t++) {
                int idx = tid + t * 256;          // 0..1023
                int row = idx >> 4, c16 = idx & 15;
                uint4 v = *(uint4*)&stage[row * STG + c16 * 8];
                if (vp) {
                    int cglob = c4 * 128 + p * 64 + row;
                    int hh = cglob >> 5, dd = cglob & 31;
                    *(uint4*)&d_vt[((size_t)hh * DCOL + ss * DCH + dd) * DN + jj0 + c16 * 8] = v;
                } else {
                    int rowg = gr0 + p * 64 + row;
                    *(uint4*)&d_gh[(size_t)rowg * DHC + (c4 - 2) * 128 + c16 * 8] = v;
                }
            }
            __syncthreads();
        }
    }
}

// ---------------------------------------------------------------------------
// K2 v2: 4 pairs per warp (8 lanes each) for LN; head-dots via one fp16 mma
// per 16 pairs. Block = 256 threads = 32 pairs. Grid = DNN/32.
// ---------------------------------------------------------------------------
constexpr int K2ZS = 132;
constexpr int K2WS = 136;

__global__ void __launch_bounds__(256) k2_ln_bias_v2(const float* __restrict__ z,
                                                     const int* __restrict__ mask,
                                                     const float* __restrict__ nw,
                                                     const float* __restrict__ nb,
                                                     const float* __restrict__ Wz) {
    __shared__ __half zls[32 * K2ZS];
    __shared__ __half Wzh[8 * K2WS];
    __shared__ float nwS[128], nbS[128];

    const int tid = threadIdx.x;
    const int lane = tid & 31;
    const int wid = tid >> 5;
    const int sub = lane >> 3;
    const int li  = lane & 7;
    const int pl  = wid * 4 + sub;
    const size_t gp = (size_t)blockIdx.x * 32 + pl;

    if (tid < 128) { nwS[tid] = nw[tid]; nbS[tid] = nb[tid]; }
    {
        int n = tid >> 5, k = (tid & 31) * 4;
        float4 w4 = *(const float4*)&Wz[n * DCZ + k];
        *(__half2*)&Wzh[n * K2WS + k]     = __floats2half2_rn(w4.x, w4.y);
        *(__half2*)&Wzh[n * K2WS + k + 2] = __floats2half2_rn(w4.z, w4.w);
    }

    const float* zr = z + gp * DCZ + li * 16;
    float4 x[4];
    #pragma unroll
    for (int t = 0; t < 4; t++) x[t] = *(const float4*)&zr[t * 4];

    float s1 = 0.f, s2 = 0.f;
    #pragma unroll
    for (int t = 0; t < 4; t++) {
        s1 += x[t].x + x[t].y + x[t].z + x[t].w;
        s2 += x[t].x * x[t].x + x[t].y * x[t].y + x[t].z * x[t].z + x[t].w * x[t].w;
    }
    #pragma unroll
    for (int off = 4; off; off >>= 1) {
        s1 += __shfl_xor_sync(0xffffffffu, s1, off);
        s2 += __shfl_xor_sync(0xffffffffu, s2, off);
    }
    float mu  = s1 * (1.f / 128.f);
    float inv = rsqrtf(s2 * (1.f / 128.f) - mu * mu + 1e-5f);
    __syncthreads();

    {
        const float* xp = (const float*)x;
        #pragma unroll
        for (int c = 0; c < 16; c += 2) {
            int ch = li * 16 + c;
            float v0 = (xp[c]     - mu) * inv * nwS[ch]     + nbS[ch];
            float v1 = (xp[c + 1] - mu) * inv * nwS[ch + 1] + nbS[ch + 1];
            *(__half2*)&zls[pl * K2ZS + ch] = __floats2half2_rn(v0, v1);
        }
    }
    __syncthreads();

    if (wid < 2) {
        const int pb = wid * 16;
        const int gid = lane >> 2, tq = lane & 3;
        float acc[4] = {0.f, 0.f, 0.f, 0.f};
        #pragma unroll
        for (int k16 = 0; k16 < 8; k16++) {
            uint32_t af[4], bf[2];
            af[0] = *(const uint32_t*)&zls[(pb + gid) * K2ZS + k16 * 16 + tq * 2];
            af[1] = *(const uint32_t*)&zls[(pb + gid + 8) * K2ZS + k16 * 16 + tq * 2];
            af[2] = *(const uint32_t*)&zls[(pb + gid) * K2ZS + k16 * 16 + tq * 2 + 8];
            af[3] = *(const uint32_t*)&zls[(pb + gid + 8) * K2ZS + k16 * 16 + tq * 2 + 8];
            bf[0] = *(const uint32_t*)&Wzh[gid * K2WS + k16 * 16 + tq * 2];
            bf[1] = *(const uint32_t*)&Wzh[gid * K2WS + k16 * 16 + tq * 2 + 8];
            MMA_F16(acc, af, bf);
        }
        size_t gp0 = (size_t)blockIdx.x * 32 + pb + gid;
        float pen0 = (mask[gp0] != 0) ? 0.f : -1e6f;
        float pen1 = (mask[gp0 + 8] != 0) ? 0.f : -1e6f;
        d_b[(size_t)(tq * 2)     * DNN + gp0]     = acc[0] + pen0;
        d_b[(size_t)(tq * 2 + 1) * DNN + gp0]     = acc[1] + pen0;
        d_b[(size_t)(tq * 2)     * DNN + gp0 + 8] = acc[2] + pen1;
        d_b[(size_t)(tq * 2 + 1) * DNN + gp0 + 8] = acc[3] + pen1;
    }
}

// ---------------------------------------------------------------------------
// K3: softmax over j (768) per (h,i) row. Reads d_b f32, writes d_bh fp16.
// ---------------------------------------------------------------------------
__global__ void k3_softmax() {
    __shared__ float sd[256];
    const float* p = d_b + (size_t)blockIdx.x * DN;
    __half* q = d_bh + (size_t)blockIdx.x * DN;
    int tid = threadIdx.x;
    float x0 = p[tid], x1 = p[tid + 256], x2 = p[tid + 512];
    float mx = fmaxf(x0, fmaxf(x1, x2));
    sd[tid] = mx; __syncthreads();
    #pragma unroll
    for (int s = 128; s; s >>= 1) {
        if (tid < s) sd[tid] = fmaxf(sd[tid], sd[tid + s]);
        __syncthreads();
    }
    float bm = sd[0]; __syncthreads();
    float e0 = __expf(x0 - bm), e1 = __expf(x1 - bm), e2 = __expf(x2 - bm);
    sd[tid] = e0 + e1 + e2; __syncthreads();
    #pragma unroll
    for (int s = 128; s; s >>= 1) {
        if (tid < s) sd[tid] += sd[tid + s];
        __syncthreads();
    }
    float invs = 1.f / sd[0];
    q[tid]       = __float2half_rn(e0 * invs);
    q[tid + 256] = __float2half_rn(e1 * invs);
    q[tid + 512] = __float2half_rn(e2 * invs);
}

// ---------------------------------------------------------------------------
// K4 v5 (fp16 mma + ldmatrix + double buffer + staged coalesced epilogue).
// Unchanged from R11 (validated 333us).
// ---------------------------------------------------------------------------
constexpr int K4ST = 40;
constexpr int K4BUF = 128 * K4ST;

__global__ void __launch_bounds__(256) k4_gemm_fp16_v5() {
    __shared__ __half sall[4 * K4BUF];
    const int h = blockIdx.z;
    const __half* A = d_bh + (size_t)h * DNN;
    const __half* B = d_vt + (size_t)h * DCOL * DN;
    __half* C = d_oh + (size_t)h * DN * DCOL;
    const int bm0 = blockIdx.y * 128;
    const int bn0 = blockIdx.x * 128;
    const int tid = threadIdx.x;
    const int lane = tid & 31;
    const int wid = tid >> 5;
    const int warp_m = wid >> 2;
    const int warp_n = wid & 3;
    const int gid = lane >> 2;
    const int tq  = lane & 3;

    const int r = tid >> 1;
    const int sel = tid & 1;

    __half* As0 = sall;
    __half* Bs0 = sall + 2 * K4BUF;
    const uint32_t as_base = smem_u32(As0);
    const uint32_t bs_base = smem_u32(Bs0);
    const uint32_t a_lane = (uint32_t)((warp_m * 64 + (lane & 15)) * 80 + (lane >> 4) * 16);
    const uint32_t b_lane = (uint32_t)((warp_n * 32 + (lane & 7) + ((lane >> 4) & 1) * 8) * 80
                                       + ((lane >> 3) & 1) * 16);
    constexpr uint32_t BUFB = K4BUF * 2;

    float acc[4][4][4];
    #pragma unroll
    for (int i = 0; i < 4; i++)
        #pragma unroll
        for (int j = 0; j < 4; j++)
            #pragma unroll
            for (int rr = 0; rr < 4; rr++) acc[i][j][rr] = 0.f;

    {
        uint4 pa0 = *(const uint4*)&A[(size_t)(bm0 + r) * DN + sel * 8];
        uint4 pa1 = *(const uint4*)&A[(size_t)(bm0 + r) * DN + 16 + sel * 8];
        uint4 pb0 = *(const uint4*)&B[(size_t)(bn0 + r) * DN + sel * 8];
        uint4 pb1 = *(const uint4*)&B[(size_t)(bn0 + r) * DN + 16 + sel * 8];
        *(uint4*)&As0[r * K4ST + sel * 8] = pa0;
        *(uint4*)&As0[r * K4ST + 16 + sel * 8] = pa1;
        *(uint4*)&Bs0[r * K4ST + sel * 8] = pb0;
        *(uint4*)&Bs0[r * K4ST + 16 + sel * 8] = pb1;
    }
    __syncthreads();

    for (int c = 0; c < 24; c++) {
        const int cur = c & 1;
        const bool more = (c + 1 < 24);
        uint4 pa0, pa1, pb0, pb1;
        if (more) {
            int kn = (c + 1) * 32;
            pa0 = *(const uint4*)&A[(size_t)(bm0 + r) * DN + kn + sel * 8];
            pa1 = *(const uint4*)&A[(size_t)(bm0 + r) * DN + kn + 16 + sel * 8];
            pb0 = *(const uint4*)&B[(size_t)(bn0 + r) * DN + kn + sel * 8];
            pb1 = *(const uint4*)&B[(size_t)(bn0 + r) * DN + kn + 16 + sel * 8];
        }

        #pragma unroll
        for (int k16 = 0; k16 < 2; k16++) {
            uint32_t af[4][4], bf[4][2];
            #pragma unroll
            for (int mt = 0; mt < 4; mt++) {
                uint32_t addr = as_base + cur * BUFB + a_lane
                              + (uint32_t)(mt * 16 * 80 + k16 * 32);
                LDSM_X4(af[mt][0], af[mt][1], af[mt][2], af[mt][3], addr);
            }
            #pragma unroll
            for (int ntp = 0; ntp < 2; ntp++) {
                uint32_t addr = bs_base + cur * BUFB + b_lane
                              + (uint32_t)(ntp * 16 * 80 + k16 * 32);
                LDSM_X4(bf[2 * ntp][0], bf[2 * ntp][1], bf[2 * ntp + 1][0], bf[2 * ntp + 1][1], addr);
            }
            #pragma unroll
            for (int mt = 0; mt < 4; mt++)
                #pragma unroll
                for (int nt = 0; nt < 4; nt++)
                    MMA_F16(acc[mt][nt], af[mt], bf[nt]);
        }

        if (more) {
            __half* An = sall + (cur ^ 1) * K4BUF;
            __half* Bn = sall + (2 + (cur ^ 1)) * K4BUF;
            *(uint4*)&An[r * K4ST + sel * 8] = pa0;
            *(uint4*)&An[r * K4ST + 16 + sel * 8] = pa1;
            *(uint4*)&Bn[r * K4ST + sel * 8] = pb0;
            *(uint4*)&Bn[r * K4ST + 16 + sel * 8] = pb1;
        }
        __syncthreads();
    }

    __half* stage = sall;
    #pragma unroll
    for (int mt = 0; mt < 4; mt++) {
        #pragma unroll
        for (int half = 0; half < 2; half++) {
            int rloc = warp_m * 64 + mt * 16 + gid + half * 8;
            #pragma unroll
            for (int nt = 0; nt < 4; nt++) {
                int cloc = warp_n * 32 + nt * 8 + tq * 2;
                *(__half2*)&stage[rloc * STG + cloc] =
                    __floats2half2_rn(acc[mt][nt][half * 2], acc[mt][nt][half * 2 + 1]);
            }
        }
    }
    __syncthreads();
    #pragma unroll
    for (int t = 0; t < 8; t++) {
        int idx = tid + t * 256;
        int row = idx >> 4, c16 = idx & 15;
        uint4 v = *(uint4*)&stage[row * STG + c16 * 8];
        *(uint4*)&C[(size_t)(bm0 + row) * DCOL + bn0 + c16 * 8] = v;
    }
}

// ---------------------------------------------------------------------------
// K5 (fp16 mma): out[128 x 64] = (g*o_gather)[128 x 256] @ WoT[256 x 64]
// Wo staged via uint4 from pre-converted fp16.
// ---------------------------------------------------------------------------
constexpr int K5ST = 72;
constexpr int K5_SMEM = (128 * K5ST + 64 * K5ST) * 2;

__global__ void k5_out_fp16(float* __restrict__ out) {
    extern __shared__ __half sm5h[];
    __half* As = sm5h;                  // [128][64] stride 72
    __half* Bs = As + 128 * K5ST;       // [64][64]  stride 72

    const int tid = threadIdx.x;
    const int gr0 = blockIdx.x * 128;
    const int ss = gr0 / DN;
    const int i0 = gr0 - ss * DN;

    const int lane = tid & 31;
    const int wid  = tid >> 5;
    const int warp_m = wid >> 1;
    const int warp_n = wid & 1;
    const int gid = lane >> 2;
    const int tq  = lane & 3;

    float acc[2][4][4];
    #pragma unroll
    for (int i = 0; i < 2; i++)
        #pragma unroll
        for (int j = 0; j < 4; j++)
            #pragma unroll
            for (int r = 0; r < 4; r++) acc[i][j][r] = 0.f;

    for (int ck0 = 0; ck0 < DHC; ck0 += 64) {
        #pragma unroll
        for (int t = 0; t < 2; t++) {
            int idx = tid + t * 256;         // 0..511
            int n = idx >> 3, c8 = (idx & 7) * 8;
            *(uint4*)&Bs[n * K5ST + c8] = *(const uint4*)&d_woh[n * DHC + ck0 + c8];
        }
        #pragma unroll
        for (int t = 0; t < 16; t++) {
            int idx = tid + t * 256;
            int r = idx >> 5;
            int cl = (idx & 31) * 2;
            int c = ck0 + cl;
            int h = c >> 5, d = c & 31;
            __half2 ov = *(const __half2*)&d_oh[((size_t)(h * DN + i0 + r) * DS + ss) * DCH + d];
            __half2 gv = *(const __half2*)&d_gh[(size_t)(gr0 + r) * DHC + c];
            float2 of = __half22float2(ov);
            float2 gf = __half22float2(gv);
            *(__half2*)&As[r * K5ST + cl] =
                __floats2half2_rn(gf.x * of.x, gf.y * of.y);
        }
        __syncthreads();

        #pragma unroll
        for (int k16 = 0; k16 < 4; k16++) {
            uint32_t af[2][4], bf[4][2];
            #pragma unroll
            for (int mt = 0; mt < 2; mt++) {
                int row = warp_m * 32 + mt * 16 + gid;
                af[mt][0] = *(const uint32_t*)&As[row * K5ST + k16 * 16 + tq * 2];
                af[mt][1] = *(const uint32_t*)&As[(row + 8) * K5ST + k16 * 16 + tq * 2];
                af[mt][2] = *(const uint32_t*)&As[row * K5ST + k16 * 16 + tq * 2 + 8];
                af[mt][3] = *(const uint32_t*)&As[(row + 8) * K5ST + k16 * 16 + tq * 2 + 8];
            }
            #pragma unroll
            for (int nt = 0; nt < 4; nt++) {
                int col = warp_n * 32 + nt * 8 + gid;
                bf[nt][0] = *(const uint32_t*)&Bs[col * K5ST + k16 * 16 + tq * 2];
                bf[nt][1] = *(const uint32_t*)&Bs[col * K5ST + k16 * 16 + tq * 2 + 8];
            }
            #pragma unroll
            for (int mt = 0; mt < 2; mt++)
                #pragma unroll
                for (int nt = 0; nt < 4; nt++)
                    MMA_F16(acc[mt][nt], af[mt], bf[nt]);
        }
        __syncthreads();
    }

    #pragma unroll
    for (int mt = 0; mt < 2; mt++) {
        #pragma unroll
        for (int nt = 0; nt < 4; nt++) {
            int row = gr0 + warp_m * 32 + mt * 16 + gid;
            int col = warp_n * 32 + nt * 8 + tq * 2;
            *(float2*)&out[(size_t)row * DCM + col] =
                make_float2(acc[mt][nt][0], acc[mt][nt][1]);
            *(float2*)&out[(size_t)(row + 8) * DCM + col] =
                make_float2(acc[mt][nt][2], acc[mt][nt][3]);
        }
    }
}

// ---------------------------------------------------------------------------
extern "C" void kernel_launch(void* const* d_in, const int* in_sizes, int n_in,
                              void* d_out, int out_size) {
    const float* m    = (const float*)d_in[0];
    const float* z    = (const float*)d_in[1];
    const int*   mask = (const int*)d_in[2];
    const float* nmw  = (const float*)d_in[3];
    const float* nmb  = (const float*)d_in[4];
    const float* nzw  = (const float*)d_in[5];
    const float* nzb  = (const float*)d_in[6];
    const float* Wm   = (const float*)d_in[7];
    const float* Wg   = (const float*)d_in[8];
    const float* Wz   = (const float*)d_in[9];
    const float* Wo   = (const float*)d_in[10];
    float* out = (float*)d_out;

    cudaFuncSetAttribute(k1_ln_vg_v4, cudaFuncAttributeMaxDynamicSharedMemorySize, K1_SMEM);
    cudaFuncSetAttribute(k5_out_fp16, cudaFuncAttributeMaxDynamicSharedMemorySize, K5_SMEM);

    k0_convert_w<<<64, 256>>>(Wm, Wg, Wo);
    k1_ln_vg_v4<<<DSN / 128, 256, K1_SMEM>>>(m, nmw, nmb);
    k2_ln_bias_v2<<<DNN / 32, 256>>>(z, mask, nzw, nzb, Wz);
    k3_softmax<<<DH * DN, 256>>>();
    dim3 g4(DCOL / 128, DN / 128, DH);
    k4_gemm_fp16_v5<<<g4, 256>>>();
    k5_out_fp16<<<DSN / 128, 256, K5_SMEM>>>(out);
}

// round 14
// speedup vs baseline: 1.0677x; 1.0677x over previous
#include <cuda_runtime.h>
#include <cuda_fp16.h>
#include <math.h>
#include <stdint.h>

// Dims
constexpr int DS  = 256;   // S
constexpr int DN  = 768;   // N
constexpr int DCM = 64;    // CM
constexpr int DCZ = 128;   // CZ
constexpr int DH  = 8;     // heads
constexpr int DCH = 32;    // per-head channels
constexpr int DHC = 256;   // H*CH
constexpr int DSN = DS * DN;          // 196608 rows of m
constexpr int DNN = DN * DN;          // 589824 pairs
constexpr int DCOL = DS * DCH;        // 8192 GEMM cols

// Scratch (device globals; no allocations allowed)
__device__ __half d_vt[(size_t)DH * DCOL * DN];  // v^T fp16: [h][n=s*32+d][j]
__device__ __half d_bh[(size_t)DH * DNN];        // softmax probs fp16: [h][i][j]
__device__ __half d_gh[(size_t)DSN * DHC];       // gate fp16: [s*N+j][hc]
__device__ float  d_b[(size_t)DH * DNN];         // logits f32 (K2 -> K3)
__device__ __half d_oh[(size_t)DH * DN * DCOL];  // o fp16: [h][i][s*32+d]
__device__ __half d_wmh[DHC * DCM];              // Wm fp16
__device__ __half d_wgh[DHC * DCM];              // Wg fp16
__device__ __half d_woh[DCM * DHC];              // Wo fp16

__device__ __forceinline__ uint32_t smem_u32(const void* p) {
    uint32_t a;
    asm("{ .reg .u64 t; cvta.to.shared.u64 t, %1; cvt.u32.u64 %0, t; }"
        : "=r"(a) : "l"(p));
    return a;
}

#define MMA_F16(acc, af, bf)                                                  \
    asm volatile(                                                             \
        "mma.sync.aligned.m16n8k16.row.col.f32.f16.f16.f32 "                  \
        "{%0,%1,%2,%3}, {%4,%5,%6,%7}, {%8,%9}, {%0,%1,%2,%3};"               \
        : "+f"((acc)[0]), "+f"((acc)[1]), "+f"((acc)[2]), "+f"((acc)[3])      \
        : "r"((af)[0]), "r"((af)[1]), "r"((af)[2]), "r"((af)[3]),             \
          "r"((bf)[0]), "r"((bf)[1]))

#define LDSM_X4(r0, r1, r2, r3, addr)                                         \
    asm volatile("ldmatrix.sync.aligned.m8n8.x4.shared.b16 {%0,%1,%2,%3}, [%4];" \
        : "=r"(r0), "=r"(r1), "=r"(r2), "=r"(r3) : "r"(addr))

constexpr int STG = 136;   // staged-epilogue stride (halfs): 272 B, 16B-aligned rows

// ---------------------------------------------------------------------------
// K0: one-time weight conversion f32 -> fp16 (Wm, Wg, Wo). Grid 64 x 256.
// ---------------------------------------------------------------------------
__global__ void k0_convert_w(const float* __restrict__ Wm,
                             const float* __restrict__ Wg,
                             const float* __restrict__ Wo) {
    int idx = blockIdx.x * 256 + threadIdx.x;   // 0..16383
    d_wmh[idx] = __float2half_rn(Wm[idx]);
    d_wgh[idx] = __float2half_rn(Wg[idx]);
    d_woh[idx] = __float2half_rn(Wo[idx]);
}

// ---------------------------------------------------------------------------
// K1 v3 (fp16 mma, single pass, coalesced staged epilogue) — R11 structure,
// W staged via uint4 from pre-converted fp16.
// ---------------------------------------------------------------------------
constexpr int K1MH = 72;   // halfs per row (144 B stride, ldmatrix conflict-free)
constexpr int K1_SMEM = 128 * 68 * 4 + 2 * (128 * K1MH * 2) + 128 * 4;  // 72192

__global__ void __launch_bounds__(256) k1_ln_vg_v3(const float* __restrict__ m,
                                                   const float* __restrict__ nw,
                                                   const float* __restrict__ nb) {
    extern __shared__ char sm1raw[];
    float*  As  = (float*)sm1raw;                                    // [128][68]
    __half* mh  = (__half*)(sm1raw + 128 * 68 * 4);                  // [128][72]
    __half* Wh  = (__half*)(sm1raw + 128 * 68 * 4 + 128 * K1MH * 2); // [128][72]
    float*  snw = (float*)(sm1raw + 128 * 68 * 4 + 2 * 128 * K1MH * 2);
    float*  snb = snw + 64;
    __half* stage = (__half*)sm1raw;   // reuse As region after LN: [128][136] = 34816B exact

    const int tid = threadIdx.x;
    const int gr0 = blockIdx.x * 128;

    // load m tile [128][64]
    #pragma unroll
    for (int t = 0; t < 8; t++) {
        int f = tid + t * 256;
        int r = f >> 4;
        int k = (f & 15) << 2;
        float4 v4 = *(const float4*)&m[(size_t)(gr0 + r) * DCM + k];
        *(float4*)&As[r * 68 + k] = v4;
    }
    if (tid < 64) { snw[tid] = nw[tid]; snb[tid] = nb[tid]; }
    __syncthreads();

    // LN -> mh fp16
    if (tid < 128) {
        float s1 = 0.f, s2 = 0.f;
        #pragma unroll
        for (int k = 0; k < 64; k++) {
            float x = As[tid * 68 + k];
            s1 += x; s2 += x * x;
        }
        float mu  = s1 * (1.f / 64.f);
        float var = s2 * (1.f / 64.f) - mu * mu;
        float inv = rsqrtf(var + 1e-5f);
        #pragma unroll
        for (int k = 0; k < 64; k += 2) {
            float x0 = (As[tid * 68 + k]     - mu) * inv * snw[k]     + snb[k];
            float x1 = (As[tid * 68 + k + 1] - mu) * inv * snw[k + 1] + snb[k + 1];
            *(__half2*)&mh[tid * K1MH + k] = __floats2half2_rn(x0, x1);
        }
    }
    __syncthreads();

    const int lane = tid & 31;
    const int wid  = tid >> 5;
    const int warp_m = wid >> 2;   // 0..1
    const int warp_n = wid & 3;    // 0..3
    const int gid = lane >> 2;
    const int tq  = lane & 3;

    const uint32_t mh_base = smem_u32(mh);
    const uint32_t wh_base = smem_u32(Wh);
    const uint32_t a_lane = (uint32_t)((warp_m * 64 + (lane & 15)) * 144 + (lane >> 4) * 16);
    const uint32_t b_lane = (uint32_t)((warp_n * 32 + (lane & 7) + ((lane >> 4) & 1) * 8) * 144
                                       + ((lane >> 3) & 1) * 16);

    const int ss = gr0 / DN;
    const int jj0 = gr0 - ss * DN;   // 768 % 128 == 0: no straddle

    for (int c4 = 0; c4 < 4; c4++) {
        const bool vp = (c4 < 2);
        const __half* Wsrc = vp ? (d_wmh + (size_t)(c4 * 128) * DCM)
                                : (d_wgh + (size_t)((c4 - 2) * 128) * DCM);
        // stage Wh[n][k] via uint4 copies from pre-converted fp16
        #pragma unroll
        for (int t = 0; t < 4; t++) {
            int idx = tid + t * 256;          // 0..1023
            int n = idx >> 3, c8 = (idx & 7) * 8;
            *(uint4*)&Wh[n * K1MH + c8] = *(const uint4*)&Wsrc[n * DCM + c8];
        }
        __syncthreads();

        const uint32_t a_base = vp ? wh_base : mh_base;
        const uint32_t b_base = vp ? mh_base : wh_base;

        float acc[4][4][4];
        #pragma unroll
        for (int i = 0; i < 4; i++)
            #pragma unroll
            for (int j = 0; j < 4; j++)
                #pragma unroll
                for (int r = 0; r < 4; r++) acc[i][j][r] = 0.f;

        #pragma unroll
        for (int k16 = 0; k16 < 4; k16++) {
            uint32_t af[4][4], bf[4][2];
            #pragma unroll
            for (int mt = 0; mt < 4; mt++) {
                uint32_t addr = a_base + a_lane + (uint32_t)(mt * 16 * 144 + k16 * 32);
                LDSM_X4(af[mt][0], af[mt][1], af[mt][2], af[mt][3], addr);
            }
            #pragma unroll
            for (int ntp = 0; ntp < 2; ntp++) {
                uint32_t addr = b_base + b_lane + (uint32_t)(ntp * 16 * 144 + k16 * 32);
                LDSM_X4(bf[2 * ntp][0], bf[2 * ntp][1], bf[2 * ntp + 1][0], bf[2 * ntp + 1][1], addr);
            }
            #pragma unroll
            for (int mt = 0; mt < 4; mt++)
                #pragma unroll
                for (int nt = 0; nt < 4; nt++)
                    MMA_F16(acc[mt][nt], af[mt], bf[nt]);
        }

        // stage acc into smem (stride 136 halfs = 272B, 16B-aligned rows)
        #pragma unroll
        for (int mt = 0; mt < 4; mt++) {
            #pragma unroll
            for (int half = 0; half < 2; half++) {
                int rloc = warp_m * 64 + mt * 16 + gid + half * 8;
                #pragma unroll
                for (int nt = 0; nt < 4; nt++) {
                    int cloc = warp_n * 32 + nt * 8 + tq * 2;
                    float c0 = acc[mt][nt][half * 2];
                    float c1 = acc[mt][nt][half * 2 + 1];
                    if (!vp) {
                        c0 = 1.f / (1.f + __expf(-c0));
                        c1 = 1.f / (1.f + __expf(-c1));
                    }
                    *(__half2*)&stage[rloc * STG + cloc] = __floats2half2_rn(c0, c1);
                }
            }
        }
        __syncthreads();

        if (vp) {
            // stage rows = channel cols; write d_vt rows (256B contiguous in j)
            #pragma unroll
            for (int t = 0; t < 8; t++) {
                int idx = tid + t * 256;          // 0..2047
                int row = idx >> 4, c16 = idx & 15;
                int cglob = c4 * 128 + row;
                int hh = cglob >> 5, dd = cglob & 31;
                uint4 v = *(uint4*)&stage[row * STG + c16 * 8];
                *(uint4*)&d_vt[((size_t)hh * DCOL + ss * DCH + dd) * DN + jj0 + c16 * 8] = v;
            }
        } else {
            // stage rows = m-rows; write d_gh rows (256B contiguous in channels)
            #pragma unroll
            for (int t = 0; t < 8; t++) {
                int idx = tid + t * 256;
                int row = idx >> 4, c16 = idx & 15;
                uint4 v = *(uint4*)&stage[row * STG + c16 * 8];
                *(uint4*)&d_gh[(size_t)(gr0 + row) * DHC + (c4 - 2) * 128 + c16 * 8] = v;
            }
        }
        __syncthreads();
    }
}

// ---------------------------------------------------------------------------
// K2 v2: 4 pairs per warp (8 lanes each) for LN; head-dots via one fp16 mma
// per 16 pairs. Block = 256 threads = 32 pairs. Grid = DNN/32.
// ---------------------------------------------------------------------------
constexpr int K2ZS = 132;
constexpr int K2WS = 136;

__global__ void __launch_bounds__(256) k2_ln_bias_v2(const float* __restrict__ z,
                                                     const int* __restrict__ mask,
                                                     const float* __restrict__ nw,
                                                     const float* __restrict__ nb,
                                                     const float* __restrict__ Wz) {
    __shared__ __half zls[32 * K2ZS];
    __shared__ __half Wzh[8 * K2WS];
    __shared__ float nwS[128], nbS[128];

    const int tid = threadIdx.x;
    const int lane = tid & 31;
    const int wid = tid >> 5;
    const int sub = lane >> 3;
    const int li  = lane & 7;
    const int pl  = wid * 4 + sub;
    const size_t gp = (size_t)blockIdx.x * 32 + pl;

    if (tid < 128) { nwS[tid] = nw[tid]; nbS[tid] = nb[tid]; }
    {
        int n = tid >> 5, k = (tid & 31) * 4;
        float4 w4 = *(const float4*)&Wz[n * DCZ + k];
        *(__half2*)&Wzh[n * K2WS + k]     = __floats2half2_rn(w4.x, w4.y);
        *(__half2*)&Wzh[n * K2WS + k + 2] = __floats2half2_rn(w4.z, w4.w);
    }

    const float* zr = z + gp * DCZ + li * 16;
    float4 x[4];
    #pragma unroll
    for (int t = 0; t < 4; t++) x[t] = *(const float4*)&zr[t * 4];

    float s1 = 0.f, s2 = 0.f;
    #pragma unroll
    for (int t = 0; t < 4; t++) {
        s1 += x[t].x + x[t].y + x[t].z + x[t].w;
        s2 += x[t].x * x[t].x + x[t].y * x[t].y + x[t].z * x[t].z + x[t].w * x[t].w;
    }
    #pragma unroll
    for (int off = 4; off; off >>= 1) {
        s1 += __shfl_xor_sync(0xffffffffu, s1, off);
        s2 += __shfl_xor_sync(0xffffffffu, s2, off);
    }
    float mu  = s1 * (1.f / 128.f);
    float inv = rsqrtf(s2 * (1.f / 128.f) - mu * mu + 1e-5f);
    __syncthreads();

    {
        const float* xp = (const float*)x;
        #pragma unroll
        for (int c = 0; c < 16; c += 2) {
            int ch = li * 16 + c;
            float v0 = (xp[c]     - mu) * inv * nwS[ch]     + nbS[ch];
            float v1 = (xp[c + 1] - mu) * inv * nwS[ch + 1] + nbS[ch + 1];
            *(__half2*)&zls[pl * K2ZS + ch] = __floats2half2_rn(v0, v1);
        }
    }
    __syncthreads();

    if (wid < 2) {
        const int pb = wid * 16;
        const int gid = lane >> 2, tq = lane & 3;
        float acc[4] = {0.f, 0.f, 0.f, 0.f};
        #pragma unroll
        for (int k16 = 0; k16 < 8; k16++) {
            uint32_t af[4], bf[2];
            af[0] = *(const uint32_t*)&zls[(pb + gid) * K2ZS + k16 * 16 + tq * 2];
            af[1] = *(const uint32_t*)&zls[(pb + gid + 8) * K2ZS + k16 * 16 + tq * 2];
            af[2] = *(const uint32_t*)&zls[(pb + gid) * K2ZS + k16 * 16 + tq * 2 + 8];
            af[3] = *(const uint32_t*)&zls[(pb + gid + 8) * K2ZS + k16 * 16 + tq * 2 + 8];
            bf[0] = *(const uint32_t*)&Wzh[gid * K2WS + k16 * 16 + tq * 2];
            bf[1] = *(const uint32_t*)&Wzh[gid * K2WS + k16 * 16 + tq * 2 + 8];
            MMA_F16(acc, af, bf);
        }
        size_t gp0 = (size_t)blockIdx.x * 32 + pb + gid;
        float pen0 = (mask[gp0] != 0) ? 0.f : -1e6f;
        float pen1 = (mask[gp0 + 8] != 0) ? 0.f : -1e6f;
        d_b[(size_t)(tq * 2)     * DNN + gp0]     = acc[0] + pen0;
        d_b[(size_t)(tq * 2 + 1) * DNN + gp0]     = acc[1] + pen0;
        d_b[(size_t)(tq * 2)     * DNN + gp0 + 8] = acc[2] + pen1;
        d_b[(size_t)(tq * 2 + 1) * DNN + gp0 + 8] = acc[3] + pen1;
    }
}

// ---------------------------------------------------------------------------
// K3: softmax over j (768) per (h,i) row. Reads d_b f32, writes d_bh fp16.
// ---------------------------------------------------------------------------
__global__ void k3_softmax() {
    __shared__ float sd[256];
    const float* p = d_b + (size_t)blockIdx.x * DN;
    __half* q = d_bh + (size_t)blockIdx.x * DN;
    int tid = threadIdx.x;
    float x0 = p[tid], x1 = p[tid + 256], x2 = p[tid + 512];
    float mx = fmaxf(x0, fmaxf(x1, x2));
    sd[tid] = mx; __syncthreads();
    #pragma unroll
    for (int s = 128; s; s >>= 1) {
        if (tid < s) sd[tid] = fmaxf(sd[tid], sd[tid + s]);
        __syncthreads();
    }
    float bm = sd[0]; __syncthreads();
    float e0 = __expf(x0 - bm), e1 = __expf(x1 - bm), e2 = __expf(x2 - bm);
    sd[tid] = e0 + e1 + e2; __syncthreads();
    #pragma unroll
    for (int s = 128; s; s >>= 1) {
        if (tid < s) sd[tid] += sd[tid + s];
        __syncthreads();
    }
    float invs = 1.f / sd[0];
    q[tid]       = __float2half_rn(e0 * invs);
    q[tid + 256] = __float2half_rn(e1 * invs);
    q[tid + 512] = __float2half_rn(e2 * invs);
}

// ---------------------------------------------------------------------------
// K4 v5 (fp16 mma + ldmatrix + double buffer + staged coalesced epilogue).
// Unchanged from R11 (validated 333us).
// ---------------------------------------------------------------------------
constexpr int K4ST = 40;
constexpr int K4BUF = 128 * K4ST;

__global__ void __launch_bounds__(256) k4_gemm_fp16_v5() {
    __shared__ __half sall[4 * K4BUF];
    const int h = blockIdx.z;
    const __half* A = d_bh + (size_t)h * DNN;
    const __half* B = d_vt + (size_t)h * DCOL * DN;
    __half* C = d_oh + (size_t)h * DN * DCOL;
    const int bm0 = blockIdx.y * 128;
    const int bn0 = blockIdx.x * 128;
    const int tid = threadIdx.x;
    const int lane = tid & 31;
    const int wid = tid >> 5;
    const int warp_m = wid >> 2;
    const int warp_n = wid & 3;
    const int gid = lane >> 2;
    const int tq  = lane & 3;

    const int r = tid >> 1;
    const int sel = tid & 1;

    __half* As0 = sall;
    __half* Bs0 = sall + 2 * K4BUF;
    const uint32_t as_base = smem_u32(As0);
    const uint32_t bs_base = smem_u32(Bs0);
    const uint32_t a_lane = (uint32_t)((warp_m * 64 + (lane & 15)) * 80 + (lane >> 4) * 16);
    const uint32_t b_lane = (uint32_t)((warp_n * 32 + (lane & 7) + ((lane >> 4) & 1) * 8) * 80
                                       + ((lane >> 3) & 1) * 16);
    constexpr uint32_t BUFB = K4BUF * 2;

    float acc[4][4][4];
    #pragma unroll
    for (int i = 0; i < 4; i++)
        #pragma unroll
        for (int j = 0; j < 4; j++)
            #pragma unroll
            for (int rr = 0; rr < 4; rr++) acc[i][j][rr] = 0.f;

    {
        uint4 pa0 = *(const uint4*)&A[(size_t)(bm0 + r) * DN + sel * 8];
        uint4 pa1 = *(const uint4*)&A[(size_t)(bm0 + r) * DN + 16 + sel * 8];
        uint4 pb0 = *(const uint4*)&B[(size_t)(bn0 + r) * DN + sel * 8];
        uint4 pb1 = *(const uint4*)&B[(size_t)(bn0 + r) * DN + 16 + sel * 8];
        *(uint4*)&As0[r * K4ST + sel * 8] = pa0;
        *(uint4*)&As0[r * K4ST + 16 + sel * 8] = pa1;
        *(uint4*)&Bs0[r * K4ST + sel * 8] = pb0;
        *(uint4*)&Bs0[r * K4ST + 16 + sel * 8] = pb1;
    }
    __syncthreads();

    for (int c = 0; c < 24; c++) {
        const int cur = c & 1;
        const bool more = (c + 1 < 24);
        uint4 pa0, pa1, pb0, pb1;
        if (more) {
            int kn = (c + 1) * 32;
            pa0 = *(const uint4*)&A[(size_t)(bm0 + r) * DN + kn + sel * 8];
            pa1 = *(const uint4*)&A[(size_t)(bm0 + r) * DN + kn + 16 + sel * 8];
            pb0 = *(const uint4*)&B[(size_t)(bn0 + r) * DN + kn + sel * 8];
            pb1 = *(const uint4*)&B[(size_t)(bn0 + r) * DN + kn + 16 + sel * 8];
        }

        #pragma unroll
        for (int k16 = 0; k16 < 2; k16++) {
            uint32_t af[4][4], bf[4][2];
            #pragma unroll
            for (int mt = 0; mt < 4; mt++) {
                uint32_t addr = as_base + cur * BUFB + a_lane
                              + (uint32_t)(mt * 16 * 80 + k16 * 32);
                LDSM_X4(af[mt][0], af[mt][1], af[mt][2], af[mt][3], addr);
            }
            #pragma unroll
            for (int ntp = 0; ntp < 2; ntp++) {
                uint32_t addr = bs_base + cur * BUFB + b_lane
                              + (uint32_t)(ntp * 16 * 80 + k16 * 32);
                LDSM_X4(bf[2 * ntp][0], bf[2 * ntp][1], bf[2 * ntp + 1][0], bf[2 * ntp + 1][1], addr);
            }
            #pragma unroll
            for (int mt = 0; mt < 4; mt++)
                #pragma unroll
                for (int nt = 0; nt < 4; nt++)
                    MMA_F16(acc[mt][nt], af[mt], bf[nt]);
        }

        if (more) {
            __half* An = sall + (cur ^ 1) * K4BUF;
            __half* Bn = sall + (2 + (cur ^ 1)) * K4BUF;
            *(uint4*)&An[r * K4ST + sel * 8] = pa0;
            *(uint4*)&An[r * K4ST + 16 + sel * 8] = pa1;
            *(uint4*)&Bn[r * K4ST + sel * 8] = pb0;
            *(uint4*)&Bn[r * K4ST + 16 + sel * 8] = pb1;
        }
        __syncthreads();
    }

    __half* stage = sall;
    #pragma unroll
    for (int mt = 0; mt < 4; mt++) {
        #pragma unroll
        for (int half = 0; half < 2; half++) {
            int rloc = warp_m * 64 + mt * 16 + gid + half * 8;
            #pragma unroll
            for (int nt = 0; nt < 4; nt++) {
                int cloc = warp_n * 32 + nt * 8 + tq * 2;
                *(__half2*)&stage[rloc * STG + cloc] =
                    __floats2half2_rn(acc[mt][nt][half * 2], acc[mt][nt][half * 2 + 1]);
            }
        }
    }
    __syncthreads();
    #pragma unroll
    for (int t = 0; t < 8; t++) {
        int idx = tid + t * 256;
        int row = idx >> 4, c16 = idx & 15;
        uint4 v = *(uint4*)&stage[row * STG + c16 * 8];
        *(uint4*)&C[(size_t)(bm0 + row) * DCOL + bn0 + c16 * 8] = v;
    }
}

// ---------------------------------------------------------------------------
// K5 (fp16 mma): out[128 x 64] = (g*o_gather)[128 x 256] @ WoT[256 x 64]
// Wo staged via uint4 from pre-converted fp16.
// ---------------------------------------------------------------------------
constexpr int K5ST = 72;
constexpr int K5_SMEM = (128 * K5ST + 64 * K5ST) * 2;

__global__ void k5_out_fp16(float* __restrict__ out) {
    extern __shared__ __half sm5h[];
    __half* As = sm5h;                  // [128][64] stride 72
    __half* Bs = As + 128 * K5ST;       // [64][64]  stride 72

    const int tid = threadIdx.x;
    const int gr0 = blockIdx.x * 128;
    const int ss = gr0 / DN;
    const int i0 = gr0 - ss * DN;

    const int lane = tid & 31;
    const int wid  = tid >> 5;
    const int warp_m = wid >> 1;
    const int warp_n = wid & 1;
    const int gid = lane >> 2;
    const int tq  = lane & 3;

    float acc[2][4][4];
    #pragma unroll
    for (int i = 0; i < 2; i++)
        #pragma unroll
        for (int j = 0; j < 4; j++)
            #pragma unroll
            for (int r = 0; r < 4; r++) acc[i][j][r] = 0.f;

    for (int ck0 = 0; ck0 < DHC; ck0 += 64) {
        #pragma unroll
        for (int t = 0; t < 2; t++) {
            int idx = tid + t * 256;         // 0..511
            int n = idx >> 3, c8 = (idx & 7) * 8;
            *(uint4*)&Bs[n * K5ST + c8] = *(const uint4*)&d_woh[n * DHC + ck0 + c8];
        }
        #pragma unroll
        for (int t = 0; t < 16; t++) {
            int idx = tid + t * 256;
            int r = idx >> 5;
            int cl = (idx & 31) * 2;
            int c = ck0 + cl;
            int h = c >> 5, d = c & 31;
            __half2 ov = *(const __half2*)&d_oh[((size_t)(h * DN + i0 + r) * DS + ss) * DCH + d];
            __half2 gv = *(const __half2*)&d_gh[(size_t)(gr0 + r) * DHC + c];
            float2 of = __half22float2(ov);
            float2 gf = __half22float2(gv);
            *(__half2*)&As[r * K5ST + cl] =
                __floats2half2_rn(gf.x * of.x, gf.y * of.y);
        }
        __syncthreads();

        #pragma unroll
        for (int k16 = 0; k16 < 4; k16++) {
            uint32_t af[2][4], bf[4][2];
            #pragma unroll
            for (int mt = 0; mt < 2; mt++) {
                int row = warp_m * 32 + mt * 16 + gid;
                af[mt][0] = *(const uint32_t*)&As[row * K5ST + k16 * 16 + tq * 2];
                af[mt][1] = *(const uint32_t*)&As[(row + 8) * K5ST + k16 * 16 + tq * 2];
                af[mt][2] = *(const uint32_t*)&As[row * K5ST + k16 * 16 + tq * 2 + 8];
                af[mt][3] = *(const uint32_t*)&As[(row + 8) * K5ST + k16 * 16 + tq * 2 + 8];
            }
            #pragma unroll
            for (int nt = 0; nt < 4; nt++) {
                int col = warp_n * 32 + nt * 8 + gid;
                bf[nt][0] = *(const uint32_t*)&Bs[col * K5ST + k16 * 16 + tq * 2];
                bf[nt][1] = *(const uint32_t*)&Bs[col * K5ST + k16 * 16 + tq * 2 + 8];
            }
            #pragma unroll
            for (int mt = 0; mt < 2; mt++)
                #pragma unroll
                for (int nt = 0; nt < 4; nt++)
                    MMA_F16(acc[mt][nt], af[mt], bf[nt]);
        }
        __syncthreads();
    }

    #pragma unroll
    for (int mt = 0; mt < 2; mt++) {
        #pragma unroll
        for (int nt = 0; nt < 4; nt++) {
            int row = gr0 + warp_m * 32 + mt * 16 + gid;
            int col = warp_n * 32 + nt * 8 + tq * 2;
            *(float2*)&out[(size_t)row * DCM + col] =
                make_float2(acc[mt][nt][0], acc[mt][nt][1]);
            *(float2*)&out[(size_t)(row + 8) * DCM + col] =
                make_float2(acc[mt][nt][2], acc[mt][nt][3]);
        }
    }
}

// ---------------------------------------------------------------------------
extern "C" void kernel_launch(void* const* d_in, const int* in_sizes, int n_in,
                              void* d_out, int out_size) {
    const float* m    = (const float*)d_in[0];
    const float* z    = (const float*)d_in[1];
    const int*   mask = (const int*)d_in[2];
    const float* nmw  = (const float*)d_in[3];
    const float* nmb  = (const float*)d_in[4];
    const float* nzw  = (const float*)d_in[5];
    const float* nzb  = (const float*)d_in[6];
    const float* Wm   = (const float*)d_in[7];
    const float* Wg   = (const float*)d_in[8];
    const float* Wz   = (const float*)d_in[9];
    const float* Wo   = (const float*)d_in[10];
    float* out = (float*)d_out;

    cudaFuncSetAttribute(k1_ln_vg_v3, cudaFuncAttributeMaxDynamicSharedMemorySize, K1_SMEM);
    cudaFuncSetAttribute(k5_out_fp16, cudaFuncAttributeMaxDynamicSharedMemorySize, K5_SMEM);

    k0_convert_w<<<64, 256>>>(Wm, Wg, Wo);
    k1_ln_vg_v3<<<DSN / 128, 256, K1_SMEM>>>(m, nmw, nmb);
    k2_ln_bias_v2<<<DNN / 32, 256>>>(z, mask, nzw, nzb, Wz);
    k3_softmax<<<DH * DN, 256>>>();
    dim3 g4(DCOL / 128, DN / 128, DH);
    k4_gemm_fp16_v5<<<g4, 256>>>();
    k5_out_fp16<<<DSN / 128, 256, K5_SMEM>>>(out);
}

// round 15
// speedup vs baseline: 1.1054x; 1.0353x over previous
#include <cuda_runtime.h>
#include <cuda_fp16.h>
#include <math.h>
#include <stdint.h>

// Dims
constexpr int DS  = 256;   // S
constexpr int DN  = 768;   // N
constexpr int DCM = 64;    // CM
constexpr int DCZ = 128;   // CZ
constexpr int DH  = 8;     // heads
constexpr int DCH = 32;    // per-head channels
constexpr int DHC = 256;   // H*CH
constexpr int DSN = DS * DN;          // 196608 rows of m
constexpr int DNN = DN * DN;          // 589824 pairs
constexpr int DCOL = DS * DCH;        // 8192 GEMM cols

// Scratch (device globals; no allocations allowed)
__device__ __half d_vt[(size_t)DH * DCOL * DN];  // v^T fp16: [h][n=s*32+d][j]
__device__ __half d_bh[(size_t)DH * DNN];        // softmax probs fp16: [h][i][j]
__device__ __half d_gh[(size_t)DSN * DHC];       // gate fp16: [s*N+j][hc]
__device__ float  d_b[(size_t)DH * DNN];         // logits f32 (K2 -> K3)
__device__ __half d_oh[(size_t)DH * DN * DCOL];  // o fp16: [h][i][s*32+d]
__device__ __half d_wmh[DHC * DCM];              // Wm fp16
__device__ __half d_wgh[DHC * DCM];              // Wg fp16
__device__ __half d_woh[DCM * DHC];              // Wo fp16

__device__ __forceinline__ uint32_t smem_u32(const void* p) {
    uint32_t a;
    asm("{ .reg .u64 t; cvta.to.shared.u64 t, %1; cvt.u32.u64 %0, t; }"
        : "=r"(a) : "l"(p));
    return a;
}

#define MMA_F16(acc, af, bf)                                                  \
    asm volatile(                                                             \
        "mma.sync.aligned.m16n8k16.row.col.f32.f16.f16.f32 "                  \
        "{%0,%1,%2,%3}, {%4,%5,%6,%7}, {%8,%9}, {%0,%1,%2,%3};"               \
        : "+f"((acc)[0]), "+f"((acc)[1]), "+f"((acc)[2]), "+f"((acc)[3])      \
        : "r"((af)[0]), "r"((af)[1]), "r"((af)[2]), "r"((af)[3]),             \
          "r"((bf)[0]), "r"((bf)[1]))

#define LDSM_X4(r0, r1, r2, r3, addr)                                         \
    asm volatile("ldmatrix.sync.aligned.m8n8.x4.shared.b16 {%0,%1,%2,%3}, [%4];" \
        : "=r"(r0), "=r"(r1), "=r"(r2), "=r"(r3) : "r"(addr))

constexpr int STG = 136;   // K1 staged-epilogue stride (halfs)

// ---------------------------------------------------------------------------
// K0: one-time weight conversion f32 -> fp16 (Wm, Wg, Wo). Grid 64 x 256.
// ---------------------------------------------------------------------------
__global__ void k0_convert_w(const float* __restrict__ Wm,
                             const float* __restrict__ Wg,
                             const float* __restrict__ Wo) {
    int idx = blockIdx.x * 256 + threadIdx.x;   // 0..16383
    d_wmh[idx] = __float2half_rn(Wm[idx]);
    d_wgh[idx] = __float2half_rn(Wg[idx]);
    d_woh[idx] = __float2half_rn(Wo[idx]);
}

// ---------------------------------------------------------------------------
// K1 v3 (fp16 mma, single pass, coalesced staged epilogue). Unchanged (R13).
// ---------------------------------------------------------------------------
constexpr int K1MH = 72;
constexpr int K1_SMEM = 128 * 68 * 4 + 2 * (128 * K1MH * 2) + 128 * 4;  // 72192

__global__ void __launch_bounds__(256) k1_ln_vg_v3(const float* __restrict__ m,
                                                   const float* __restrict__ nw,
                                                   const float* __restrict__ nb) {
    extern __shared__ char sm1raw[];
    float*  As  = (float*)sm1raw;                                    // [128][68]
    __half* mh  = (__half*)(sm1raw + 128 * 68 * 4);                  // [128][72]
    __half* Wh  = (__half*)(sm1raw + 128 * 68 * 4 + 128 * K1MH * 2); // [128][72]
    float*  snw = (float*)(sm1raw + 128 * 68 * 4 + 2 * 128 * K1MH * 2);
    float*  snb = snw + 64;
    __half* stage = (__half*)sm1raw;   // reuse As region after LN: [128][136]

    const int tid = threadIdx.x;
    const int gr0 = blockIdx.x * 128;

    #pragma unroll
    for (int t = 0; t < 8; t++) {
        int f = tid + t * 256;
        int r = f >> 4;
        int k = (f & 15) << 2;
        float4 v4 = *(const float4*)&m[(size_t)(gr0 + r) * DCM + k];
        *(float4*)&As[r * 68 + k] = v4;
    }
    if (tid < 64) { snw[tid] = nw[tid]; snb[tid] = nb[tid]; }
    __syncthreads();

    if (tid < 128) {
        float s1 = 0.f, s2 = 0.f;
        #pragma unroll
        for (int k = 0; k < 64; k++) {
            float x = As[tid * 68 + k];
            s1 += x; s2 += x * x;
        }
        float mu  = s1 * (1.f / 64.f);
        float var = s2 * (1.f / 64.f) - mu * mu;
        float inv = rsqrtf(var + 1e-5f);
        #pragma unroll
        for (int k = 0; k < 64; k += 2) {
            float x0 = (As[tid * 68 + k]     - mu) * inv * snw[k]     + snb[k];
            float x1 = (As[tid * 68 + k + 1] - mu) * inv * snw[k + 1] + snb[k + 1];
            *(__half2*)&mh[tid * K1MH + k] = __floats2half2_rn(x0, x1);
        }
    }
    __syncthreads();

    const int lane = tid & 31;
    const int wid  = tid >> 5;
    const int warp_m = wid >> 2;
    const int warp_n = wid & 3;
    const int gid = lane >> 2;
    const int tq  = lane & 3;

    const uint32_t mh_base = smem_u32(mh);
    const uint32_t wh_base = smem_u32(Wh);
    const uint32_t a_lane = (uint32_t)((warp_m * 64 + (lane & 15)) * 144 + (lane >> 4) * 16);
    const uint32_t b_lane = (uint32_t)((warp_n * 32 + (lane & 7) + ((lane >> 4) & 1) * 8) * 144
                                       + ((lane >> 3) & 1) * 16);

    const int ss = gr0 / DN;
    const int jj0 = gr0 - ss * DN;

    for (int c4 = 0; c4 < 4; c4++) {
        const bool vp = (c4 < 2);
        const __half* Wsrc = vp ? (d_wmh + (size_t)(c4 * 128) * DCM)
                                : (d_wgh + (size_t)((c4 - 2) * 128) * DCM);
        #pragma unroll
        for (int t = 0; t < 4; t++) {
            int idx = tid + t * 256;
            int n = idx >> 3, c8 = (idx & 7) * 8;
            *(uint4*)&Wh[n * K1MH + c8] = *(const uint4*)&Wsrc[n * DCM + c8];
        }
        __syncthreads();

        const uint32_t a_base = vp ? wh_base : mh_base;
        const uint32_t b_base = vp ? mh_base : wh_base;

        float acc[4][4][4];
        #pragma unroll
        for (int i = 0; i < 4; i++)
            #pragma unroll
            for (int j = 0; j < 4; j++)
                #pragma unroll
                for (int r = 0; r < 4; r++) acc[i][j][r] = 0.f;

        #pragma unroll
        for (int k16 = 0; k16 < 4; k16++) {
            uint32_t af[4][4], bf[4][2];
            #pragma unroll
            for (int mt = 0; mt < 4; mt++) {
                uint32_t addr = a_base + a_lane + (uint32_t)(mt * 16 * 144 + k16 * 32);
                LDSM_X4(af[mt][0], af[mt][1], af[mt][2], af[mt][3], addr);
            }
            #pragma unroll
            for (int ntp = 0; ntp < 2; ntp++) {
                uint32_t addr = b_base + b_lane + (uint32_t)(ntp * 16 * 144 + k16 * 32);
                LDSM_X4(bf[2 * ntp][0], bf[2 * ntp][1], bf[2 * ntp + 1][0], bf[2 * ntp + 1][1], addr);
            }
            #pragma unroll
            for (int mt = 0; mt < 4; mt++)
                #pragma unroll
                for (int nt = 0; nt < 4; nt++)
                    MMA_F16(acc[mt][nt], af[mt], bf[nt]);
        }

        #pragma unroll
        for (int mt = 0; mt < 4; mt++) {
            #pragma unroll
            for (int half = 0; half < 2; half++) {
                int rloc = warp_m * 64 + mt * 16 + gid + half * 8;
                #pragma unroll
                for (int nt = 0; nt < 4; nt++) {
                    int cloc = warp_n * 32 + nt * 8 + tq * 2;
                    float c0 = acc[mt][nt][half * 2];
                    float c1 = acc[mt][nt][half * 2 + 1];
                    if (!vp) {
                        c0 = 1.f / (1.f + __expf(-c0));
                        c1 = 1.f / (1.f + __expf(-c1));
                    }
                    *(__half2*)&stage[rloc * STG + cloc] = __floats2half2_rn(c0, c1);
                }
            }
        }
        __syncthreads();

        if (vp) {
            #pragma unroll
            for (int t = 0; t < 8; t++) {
                int idx = tid + t * 256;
                int row = idx >> 4, c16 = idx & 15;
                int cglob = c4 * 128 + row;
                int hh = cglob >> 5, dd = cglob & 31;
                uint4 v = *(uint4*)&stage[row * STG + c16 * 8];
                *(uint4*)&d_vt[((size_t)hh * DCOL + ss * DCH + dd) * DN + jj0 + c16 * 8] = v;
            }
        } else {
            #pragma unroll
            for (int t = 0; t < 8; t++) {
                int idx = tid + t * 256;
                int row = idx >> 4, c16 = idx & 15;
                uint4 v = *(uint4*)&stage[row * STG + c16 * 8];
                *(uint4*)&d_gh[(size_t)(gr0 + row) * DHC + (c4 - 2) * 128 + c16 * 8] = v;
            }
        }
        __syncthreads();
    }
}

// ---------------------------------------------------------------------------
// K2 v2: unchanged (R13).
// ---------------------------------------------------------------------------
constexpr int K2ZS = 132;
constexpr int K2WS = 136;

__global__ void __launch_bounds__(256) k2_ln_bias_v2(const float* __restrict__ z,
                                                     const int* __restrict__ mask,
                                                     const float* __restrict__ nw,
                                                     const float* __restrict__ nb,
                                                     const float* __restrict__ Wz) {
    __shared__ __half zls[32 * K2ZS];
    __shared__ __half Wzh[8 * K2WS];
    __shared__ float nwS[128], nbS[128];

    const int tid = threadIdx.x;
    const int lane = tid & 31;
    const int wid = tid >> 5;
    const int sub = lane >> 3;
    const int li  = lane & 7;
    const int pl  = wid * 4 + sub;
    const size_t gp = (size_t)blockIdx.x * 32 + pl;

    if (tid < 128) { nwS[tid] = nw[tid]; nbS[tid] = nb[tid]; }
    {
        int n = tid >> 5, k = (tid & 31) * 4;
        float4 w4 = *(const float4*)&Wz[n * DCZ + k];
        *(__half2*)&Wzh[n * K2WS + k]     = __floats2half2_rn(w4.x, w4.y);
        *(__half2*)&Wzh[n * K2WS + k + 2] = __floats2half2_rn(w4.z, w4.w);
    }

    const float* zr = z + gp * DCZ + li * 16;
    float4 x[4];
    #pragma unroll
    for (int t = 0; t < 4; t++) x[t] = *(const float4*)&zr[t * 4];

    float s1 = 0.f, s2 = 0.f;
    #pragma unroll
    for (int t = 0; t < 4; t++) {
        s1 += x[t].x + x[t].y + x[t].z + x[t].w;
        s2 += x[t].x * x[t].x + x[t].y * x[t].y + x[t].z * x[t].z + x[t].w * x[t].w;
    }
    #pragma unroll
    for (int off = 4; off; off >>= 1) {
        s1 += __shfl_xor_sync(0xffffffffu, s1, off);
        s2 += __shfl_xor_sync(0xffffffffu, s2, off);
    }
    float mu  = s1 * (1.f / 128.f);
    float inv = rsqrtf(s2 * (1.f / 128.f) - mu * mu + 1e-5f);
    __syncthreads();

    {
        const float* xp = (const float*)x;
        #pragma unroll
        for (int c = 0; c < 16; c += 2) {
            int ch = li * 16 + c;
            float v0 = (xp[c]     - mu) * inv * nwS[ch]     + nbS[ch];
            float v1 = (xp[c + 1] - mu) * inv * nwS[ch + 1] + nbS[ch + 1];
            *(__half2*)&zls[pl * K2ZS + ch] = __floats2half2_rn(v0, v1);
        }
    }
    __syncthreads();

    if (wid < 2) {
        const int pb = wid * 16;
        const int gid = lane >> 2, tq = lane & 3;
        float acc[4] = {0.f, 0.f, 0.f, 0.f};
        #pragma unroll
        for (int k16 = 0; k16 < 8; k16++) {
            uint32_t af[4], bf[2];
            af[0] = *(const uint32_t*)&zls[(pb + gid) * K2ZS + k16 * 16 + tq * 2];
            af[1] = *(const uint32_t*)&zls[(pb + gid + 8) * K2ZS + k16 * 16 + tq * 2];
            af[2] = *(const uint32_t*)&zls[(pb + gid) * K2ZS + k16 * 16 + tq * 2 + 8];
            af[3] = *(const uint32_t*)&zls[(pb + gid + 8) * K2ZS + k16 * 16 + tq * 2 + 8];
            bf[0] = *(const uint32_t*)&Wzh[gid * K2WS + k16 * 16 + tq * 2];
            bf[1] = *(const uint32_t*)&Wzh[gid * K2WS + k16 * 16 + tq * 2 + 8];
            MMA_F16(acc, af, bf);
        }
        size_t gp0 = (size_t)blockIdx.x * 32 + pb + gid;
        float pen0 = (mask[gp0] != 0) ? 0.f : -1e6f;
        float pen1 = (mask[gp0 + 8] != 0) ? 0.f : -1e6f;
        d_b[(size_t)(tq * 2)     * DNN + gp0]     = acc[0] + pen0;
        d_b[(size_t)(tq * 2 + 1) * DNN + gp0]     = acc[1] + pen0;
        d_b[(size_t)(tq * 2)     * DNN + gp0 + 8] = acc[2] + pen1;
        d_b[(size_t)(tq * 2 + 1) * DNN + gp0 + 8] = acc[3] + pen1;
    }
}

// ---------------------------------------------------------------------------
// K3: softmax. Unchanged (R13).
// ---------------------------------------------------------------------------
__global__ void k3_softmax() {
    __shared__ float sd[256];
    const float* p = d_b + (size_t)blockIdx.x * DN;
    __half* q = d_bh + (size_t)blockIdx.x * DN;
    int tid = threadIdx.x;
    float x0 = p[tid], x1 = p[tid + 256], x2 = p[tid + 512];
    float mx = fmaxf(x0, fmaxf(x1, x2));
    sd[tid] = mx; __syncthreads();
    #pragma unroll
    for (int s = 128; s; s >>= 1) {
        if (tid < s) sd[tid] = fmaxf(sd[tid], sd[tid + s]);
        __syncthreads();
    }
    float bm = sd[0]; __syncthreads();
    float e0 = __expf(x0 - bm), e1 = __expf(x1 - bm), e2 = __expf(x2 - bm);
    sd[tid] = e0 + e1 + e2; __syncthreads();
    #pragma unroll
    for (int s = 128; s; s >>= 1) {
        if (tid < s) sd[tid] += sd[tid + s];
        __syncthreads();
    }
    float invs = 1.f / sd[0];
    q[tid]       = __float2half_rn(e0 * invs);
    q[tid + 256] = __float2half_rn(e1 * invs);
    q[tid + 512] = __float2half_rn(e2 * invs);
}

// ---------------------------------------------------------------------------
// K4 v6: block 128x256, 8 warps (2x4), warp tile 64x64, k32 double-buffered.
// 1.5x less LDSM traffic per FLOP than 64x32. Staged coalesced epilogue.
// smem: A[2][128][40] + B[2][256][40] = 61440 B; epilogue stage [128][264]
// reuses the same region (67584 B dynamic).
// ---------------------------------------------------------------------------
constexpr int K4ST = 40;                 // halfs per staged row
constexpr int K4AB = 128 * K4ST;         // A buffer (halfs)
constexpr int K4BB = 256 * K4ST;         // B buffer (halfs)
constexpr int K4STG = 264;               // epilogue stage stride (halfs), 528B rows
constexpr int K4_SMEM = 128 * K4STG * 2; // 67584 B (>= 61440 mainloop)

__global__ void __launch_bounds__(256) k4_gemm_fp16_v6() {
    extern __shared__ __half sall[];
    const int h = blockIdx.z;
    const __half* A = d_bh + (size_t)h * DNN;
    const __half* B = d_vt + (size_t)h * DCOL * DN;
    __half* C = d_oh + (size_t)h * DN * DCOL;
    const int bm0 = blockIdx.y * 128;
    const int bn0 = blockIdx.x * 256;
    const int tid = threadIdx.x;
    const int lane = tid & 31;
    const int wid = tid >> 5;
    const int warp_m = wid >> 2;       // 0..1 -> 64 rows
    const int warp_n = wid & 3;        // 0..3 -> 64 cols
    const int gid = lane >> 2;
    const int tq  = lane & 3;

    // staging indices
    const int ra = tid >> 1;           // A row 0..127
    const int sela = tid & 1;
    const int rb = tid >> 2;           // base B row helper (unused directly)

    __half* Abuf = sall;                         // [2][128][40]
    __half* Bbuf = sall + 2 * K4AB;              // [2][256][40]
    const uint32_t as_base = smem_u32(Abuf);
    const uint32_t bs_base = smem_u32(Bbuf);
    const uint32_t a_lane = (uint32_t)((warp_m * 64 + (lane & 15)) * 80 + (lane >> 4) * 16);
    const uint32_t b_lane = (uint32_t)((warp_n * 64 + (lane & 7) + ((lane >> 4) & 1) * 8) * 80
                                       + ((lane >> 3) & 1) * 16);
    constexpr uint32_t ABUFB = K4AB * 2;   // bytes per A buffer
    constexpr uint32_t BBUFB = K4BB * 2;   // bytes per B buffer

    float acc[4][8][4];
    #pragma unroll
    for (int i = 0; i < 4; i++)
        #pragma unroll
        for (int j = 0; j < 8; j++)
            #pragma unroll
            for (int rr = 0; rr < 4; rr++) acc[i][j][rr] = 0.f;

    // stage tile 0 (k = 0..31)
    {
        *(uint4*)&Abuf[ra * K4ST + sela * 8] =
            *(const uint4*)&A[(size_t)(bm0 + ra) * DN + sela * 8];
        *(uint4*)&Abuf[ra * K4ST + 16 + sela * 8] =
            *(const uint4*)&A[(size_t)(bm0 + ra) * DN + 16 + sela * 8];
        #pragma unroll
        for (int t = 0; t < 4; t++) {
            int idx = tid + t * 256;              // 0..1023
            int row = idx >> 2, q = idx & 3;
            *(uint4*)&Bbuf[row * K4ST + q * 8] =
                *(const uint4*)&B[(size_t)(bn0 + row) * DN + q * 8];
        }
    }
    __syncthreads();

    for (int c = 0; c < 24; c++) {
        const int cur = c & 1;
        const bool more = (c + 1 < 24);
        uint4 pa0, pa1, pb[4];
        if (more) {
            int kn = (c + 1) * 32;
            pa0 = *(const uint4*)&A[(size_t)(bm0 + ra) * DN + kn + sela * 8];
            pa1 = *(const uint4*)&A[(size_t)(bm0 + ra) * DN + kn + 16 + sela * 8];
            #pragma unroll
            for (int t = 0; t < 4; t++) {
                int idx = tid + t * 256;
                int row = idx >> 2, q = idx & 3;
                pb[t] = *(const uint4*)&B[(size_t)(bn0 + row) * DN + kn + q * 8];
            }
        }

        #pragma unroll
        for (int k16 = 0; k16 < 2; k16++) {
            uint32_t af[4][4], bf[8][2];
            #pragma unroll
            for (int mt = 0; mt < 4; mt++) {
                uint32_t addr = as_base + cur * ABUFB + a_lane
                              + (uint32_t)(mt * 16 * 80 + k16 * 32);
                LDSM_X4(af[mt][0], af[mt][1], af[mt][2], af[mt][3], addr);
            }
            #pragma unroll
            for (int ntp = 0; ntp < 4; ntp++) {
                uint32_t addr = bs_base + cur * BBUFB + b_lane
                              + (uint32_t)(ntp * 16 * 80 + k16 * 32);
                LDSM_X4(bf[2 * ntp][0], bf[2 * ntp][1], bf[2 * ntp + 1][0], bf[2 * ntp + 1][1], addr);
            }
            #pragma unroll
            for (int mt = 0; mt < 4; mt++)
                #pragma unroll
                for (int nt = 0; nt < 8; nt++)
                    MMA_F16(acc[mt][nt], af[mt], bf[nt]);
        }

        if (more) {
            __half* An = Abuf + (cur ^ 1) * K4AB;
            __half* Bn = Bbuf + (cur ^ 1) * K4BB;
            *(uint4*)&An[ra * K4ST + sela * 8] = pa0;
            *(uint4*)&An[ra * K4ST + 16 + sela * 8] = pa1;
            #pragma unroll
            for (int t = 0; t < 4; t++) {
                int idx = tid + t * 256;
                int row = idx >> 2, q = idx & 3;
                *(uint4*)&Bn[row * K4ST + q * 8] = pb[t];
            }
        }
        __syncthreads();
    }

    // staged coalesced epilogue: stage [128][264] halfs (reuses sall)
    __half* stage = sall;
    #pragma unroll
    for (int mt = 0; mt < 4; mt++) {
        #pragma unroll
        for (int half = 0; half < 2; half++) {
            int rloc = warp_m * 64 + mt * 16 + gid + half * 8;
            #pragma unroll
            for (int nt = 0; nt < 8; nt++) {
                int cloc = warp_n * 64 + nt * 8 + tq * 2;
                *(__half2*)&stage[rloc * K4STG + cloc] =
                    __floats2half2_rn(acc[mt][nt][half * 2], acc[mt][nt][half * 2 + 1]);
            }
        }
    }
    __syncthreads();
    #pragma unroll
    for (int t = 0; t < 8; t++) {
        int idx = tid + t * 256;          // 0..2047
        int row = idx >> 4, c16 = idx & 15;   // 16 uint4 per 128-half half-row
        // two half-rows of 128 halfs each: pass covers 256 halfs per row via c16 0..15 + row parity
        // simpler: 2048 uint4 total = 128 rows x 16 uint4? 256 halfs/row = 32 uint4/row -> need 4096.
        // handled below
        (void)row; (void)c16;
        break;
    }
    // correct copy-out: 128 rows x 32 uint4 = 4096 uint4, 256 threads x 16 iters
    #pragma unroll
    for (int t = 0; t < 16; t++) {
        int idx = tid + t * 256;          // 0..4095
        int row = idx >> 5, c32 = idx & 31;
        uint4 v = *(uint4*)&stage[row * K4STG + c32 * 8];
        *(uint4*)&C[(size_t)(bm0 + row) * DCOL + bn0 + c32 * 8] = v;
    }
}

// ---------------------------------------------------------------------------
// K5 (fp16 mma): unchanged (R13).
// ---------------------------------------------------------------------------
constexpr int K5ST = 72;
constexpr int K5_SMEM = (128 * K5ST + 64 * K5ST) * 2;

__global__ void k5_out_fp16(float* __restrict__ out) {
    extern __shared__ __half sm5h[];
    __half* As = sm5h;
    __half* Bs = As + 128 * K5ST;

    const int tid = threadIdx.x;
    const int gr0 = blockIdx.x * 128;
    const int ss = gr0 / DN;
    const int i0 = gr0 - ss * DN;

    const int lane = tid & 31;
    const int wid  = tid >> 5;
    const int warp_m = wid >> 1;
    const int warp_n = wid & 1;
    const int gid = lane >> 2;
    const int tq  = lane & 3;

    float acc[2][4][4];
    #pragma unroll
    for (int i = 0; i < 2; i++)
        #pragma unroll
        for (int j = 0; j < 4; j++)
            #pragma unroll
            for (int r = 0; r < 4; r++) acc[i][j][r] = 0.f;

    for (int ck0 = 0; ck0 < DHC; ck0 += 64) {
        #pragma unroll
        for (int t = 0; t < 2; t++) {
            int idx = tid + t * 256;
            int n = idx >> 3, c8 = (idx & 7) * 8;
            *(uint4*)&Bs[n * K5ST + c8] = *(const uint4*)&d_woh[n * DHC + ck0 + c8];
        }
        #pragma unroll
        for (int t = 0; t < 16; t++) {
            int idx = tid + t * 256;
            int r = idx >> 5;
            int cl = (idx & 31) * 2;
            int c = ck0 + cl;
            int h = c >> 5, d = c & 31;
            __half2 ov = *(const __half2*)&d_oh[((size_t)(h * DN + i0 + r) * DS + ss) * DCH + d];
            __half2 gv = *(const __half2*)&d_gh[(size_t)(gr0 + r) * DHC + c];
            float2 of = __half22float2(ov);
            float2 gf = __half22float2(gv);
            *(__half2*)&As[r * K5ST + cl] =
                __floats2half2_rn(gf.x * of.x, gf.y * of.y);
        }
        __syncthreads();

        #pragma unroll
        for (int k16 = 0; k16 < 4; k16++) {
            uint32_t af[2][4], bf[4][2];
            #pragma unroll
            for (int mt = 0; mt < 2; mt++) {
                int row = warp_m * 32 + mt * 16 + gid;
                af[mt][0] = *(const uint32_t*)&As[row * K5ST + k16 * 16 + tq * 2];
                af[mt][1] = *(const uint32_t*)&As[(row + 8) * K5ST + k16 * 16 + tq * 2];
                af[mt][2] = *(const uint32_t*)&As[row * K5ST + k16 * 16 + tq * 2 + 8];
                af[mt][3] = *(const uint32_t*)&As[(row + 8) * K5ST + k16 * 16 + tq * 2 + 8];
            }
            #pragma unroll
            for (int nt = 0; nt < 4; nt++) {
                int col = warp_n * 32 + nt * 8 + gid;
                bf[nt][0] = *(const uint32_t*)&Bs[col * K5ST + k16 * 16 + tq * 2];
                bf[nt][1] = *(const uint32_t*)&Bs[col * K5ST + k16 * 16 + tq * 2 + 8];
            }
            #pragma unroll
            for (int mt = 0; mt < 2; mt++)
                #pragma unroll
                for (int nt = 0; nt < 4; nt++)
                    MMA_F16(acc[mt][nt], af[mt], bf[nt]);
        }
        __syncthreads();
    }

    #pragma unroll
    for (int mt = 0; mt < 2; mt++) {
        #pragma unroll
        for (int nt = 0; nt < 4; nt++) {
            int row = gr0 + warp_m * 32 + mt * 16 + gid;
            int col = warp_n * 32 + nt * 8 + tq * 2;
            *(float2*)&out[(size_t)row * DCM + col] =
                make_float2(acc[mt][nt][0], acc[mt][nt][1]);
            *(float2*)&out[(size_t)(row + 8) * DCM + col] =
                make_float2(acc[mt][nt][2], acc[mt][nt][3]);
        }
    }
}

// ---------------------------------------------------------------------------
extern "C" void kernel_launch(void* const* d_in, const int* in_sizes, int n_in,
                              void* d_out, int out_size) {
    const float* m    = (const float*)d_in[0];
    const float* z    = (const float*)d_in[1];
    const int*   mask = (const int*)d_in[2];
    const float* nmw  = (const float*)d_in[3];
    const float* nmb  = (const float*)d_in[4];
    const float* nzw  = (const float*)d_in[5];
    const float* nzb  = (const float*)d_in[6];
    const float* Wm   = (const float*)d_in[7];
    const float* Wg   = (const float*)d_in[8];
    const float* Wz   = (const float*)d_in[9];
    const float* Wo   = (const float*)d_in[10];
    float* out = (float*)d_out;

    cudaFuncSetAttribute(k1_ln_vg_v3,   cudaFuncAttributeMaxDynamicSharedMemorySize, K1_SMEM);
    cudaFuncSetAttribute(k4_gemm_fp16_v6, cudaFuncAttributeMaxDynamicSharedMemorySize, K4_SMEM);
    cudaFuncSetAttribute(k5_out_fp16,   cudaFuncAttributeMaxDynamicSharedMemorySize, K5_SMEM);

    k0_convert_w<<<64, 256>>>(Wm, Wg, Wo);
    k1_ln_vg_v3<<<DSN / 128, 256, K1_SMEM>>>(m, nmw, nmb);
    k2_ln_bias_v2<<<DNN / 32, 256>>>(z, mask, nzw, nzb, Wz);
    k3_softmax<<<DH * DN, 256>>>();
    dim3 g4(DCOL / 256, DN / 128, DH);
    k4_gemm_fp16_v6<<<g4, 256, K4_SMEM>>>();
    k5_out_fp16<<<DSN / 128, 256, K5_SMEM>>>(out);
}

// round 16
// speedup vs baseline: 1.1118x; 1.0058x over previous
#include <cuda_runtime.h>
#include <cuda_fp16.h>
#include <math.h>
#include <stdint.h>

// Dims
constexpr int DS  = 256;   // S
constexpr int DN  = 768;   // N
constexpr int DCM = 64;    // CM
constexpr int DCZ = 128;   // CZ
constexpr int DH  = 8;     // heads
constexpr int DCH = 32;    // per-head channels
constexpr int DHC = 256;   // H*CH
constexpr int DSN = DS * DN;          // 196608 rows of m
constexpr int DNN = DN * DN;          // 589824 pairs
constexpr int DCOL = DS * DCH;        // 8192 GEMM cols

// Scratch (device globals; no allocations allowed)
__device__ __half d_vt[(size_t)DH * DCOL * DN];  // v^T fp16: [h][n=s*32+d][j]
__device__ __half d_bh[(size_t)DH * DNN];        // softmax probs fp16: [h][i][j]
__device__ __half d_gh[(size_t)DSN * DHC];       // gate fp16: [s*N+j][hc]
__device__ float  d_b[(size_t)DH * DNN];         // logits f32 (K2 -> K3)
__device__ __half d_oh[(size_t)DH * DN * DCOL];  // o fp16: [h][i][s*32+d]
__device__ __half d_wmh[DHC * DCM];              // Wm fp16
__device__ __half d_wgh[DHC * DCM];              // Wg fp16
__device__ __half d_woh[DCM * DHC];              // Wo fp16

__device__ __forceinline__ uint32_t smem_u32(const void* p) {
    uint32_t a;
    asm("{ .reg .u64 t; cvta.to.shared.u64 t, %1; cvt.u32.u64 %0, t; }"
        : "=r"(a) : "l"(p));
    return a;
}

#define MMA_F16(acc, af, bf)                                                  \
    asm volatile(                                                             \
        "mma.sync.aligned.m16n8k16.row.col.f32.f16.f16.f32 "                  \
        "{%0,%1,%2,%3}, {%4,%5,%6,%7}, {%8,%9}, {%0,%1,%2,%3};"               \
        : "+f"((acc)[0]), "+f"((acc)[1]), "+f"((acc)[2]), "+f"((acc)[3])      \
        : "r"((af)[0]), "r"((af)[1]), "r"((af)[2]), "r"((af)[3]),             \
          "r"((bf)[0]), "r"((bf)[1]))

#define LDSM_X4(r0, r1, r2, r3, addr)                                         \
    asm volatile("ldmatrix.sync.aligned.m8n8.x4.shared.b16 {%0,%1,%2,%3}, [%4];" \
        : "=r"(r0), "=r"(r1), "=r"(r2), "=r"(r3) : "r"(addr))

#define CP_ASYNC16(dst, src)                                                  \
    asm volatile("cp.async.cg.shared.global [%0], [%1], 16;"                  \
        :: "r"(dst), "l"(src) : "memory")
#define CP_COMMIT() asm volatile("cp.async.commit_group;" ::: "memory")
#define CP_WAIT0()  asm volatile("cp.async.wait_group 0;" ::: "memory")

constexpr int STG = 136;   // K1 staged-epilogue stride (halfs)

// ---------------------------------------------------------------------------
// K0: one-time weight conversion f32 -> fp16 (Wm, Wg, Wo). Grid 64 x 256.
// ---------------------------------------------------------------------------
__global__ void k0_convert_w(const float* __restrict__ Wm,
                             const float* __restrict__ Wg,
                             const float* __restrict__ Wo) {
    int idx = blockIdx.x * 256 + threadIdx.x;   // 0..16383
    d_wmh[idx] = __float2half_rn(Wm[idx]);
    d_wgh[idx] = __float2half_rn(Wg[idx]);
    d_woh[idx] = __float2half_rn(Wo[idx]);
}

// ---------------------------------------------------------------------------
// K1 v3 (fp16 mma, single pass, coalesced staged epilogue). Unchanged (R13).
// ---------------------------------------------------------------------------
constexpr int K1MH = 72;
constexpr int K1_SMEM = 128 * 68 * 4 + 2 * (128 * K1MH * 2) + 128 * 4;  // 72192

__global__ void __launch_bounds__(256) k1_ln_vg_v3(const float* __restrict__ m,
                                                   const float* __restrict__ nw,
                                                   const float* __restrict__ nb) {
    extern __shared__ char sm1raw[];
    float*  As  = (float*)sm1raw;                                    // [128][68]
    __half* mh  = (__half*)(sm1raw + 128 * 68 * 4);                  // [128][72]
    __half* Wh  = (__half*)(sm1raw + 128 * 68 * 4 + 128 * K1MH * 2); // [128][72]
    float*  snw = (float*)(sm1raw + 128 * 68 * 4 + 2 * 128 * K1MH * 2);
    float*  snb = snw + 64;
    __half* stage = (__half*)sm1raw;   // reuse As region after LN: [128][136]

    const int tid = threadIdx.x;
    const int gr0 = blockIdx.x * 128;

    #pragma unroll
    for (int t = 0; t < 8; t++) {
        int f = tid + t * 256;
        int r = f >> 4;
        int k = (f & 15) << 2;
        float4 v4 = *(const float4*)&m[(size_t)(gr0 + r) * DCM + k];
        *(float4*)&As[r * 68 + k] = v4;
    }
    if (tid < 64) { snw[tid] = nw[tid]; snb[tid] = nb[tid]; }
    __syncthreads();

    if (tid < 128) {
        float s1 = 0.f, s2 = 0.f;
        #pragma unroll
        for (int k = 0; k < 64; k++) {
            float x = As[tid * 68 + k];
            s1 += x; s2 += x * x;
        }
        float mu  = s1 * (1.f / 64.f);
        float var = s2 * (1.f / 64.f) - mu * mu;
        float inv = rsqrtf(var + 1e-5f);
        #pragma unroll
        for (int k = 0; k < 64; k += 2) {
            float x0 = (As[tid * 68 + k]     - mu) * inv * snw[k]     + snb[k];
            float x1 = (As[tid * 68 + k + 1] - mu) * inv * snw[k + 1] + snb[k + 1];
            *(__half2*)&mh[tid * K1MH + k] = __floats2half2_rn(x0, x1);
        }
    }
    __syncthreads();

    const int lane = tid & 31;
    const int wid  = tid >> 5;
    const int warp_m = wid >> 2;
    const int warp_n = wid & 3;
    const int gid = lane >> 2;
    const int tq  = lane & 3;

    const uint32_t mh_base = smem_u32(mh);
    const uint32_t wh_base = smem_u32(Wh);
    const uint32_t a_lane = (uint32_t)((warp_m * 64 + (lane & 15)) * 144 + (lane >> 4) * 16);
    const uint32_t b_lane = (uint32_t)((warp_n * 32 + (lane & 7) + ((lane >> 4) & 1) * 8) * 144
                                       + ((lane >> 3) & 1) * 16);

    const int ss = gr0 / DN;
    const int jj0 = gr0 - ss * DN;

    for (int c4 = 0; c4 < 4; c4++) {
        const bool vp = (c4 < 2);
        const __half* Wsrc = vp ? (d_wmh + (size_t)(c4 * 128) * DCM)
                                : (d_wgh + (size_t)((c4 - 2) * 128) * DCM);
        #pragma unroll
        for (int t = 0; t < 4; t++) {
            int idx = tid + t * 256;
            int n = idx >> 3, c8 = (idx & 7) * 8;
            *(uint4*)&Wh[n * K1MH + c8] = *(const uint4*)&Wsrc[n * DCM + c8];
        }
        __syncthreads();

        const uint32_t a_base = vp ? wh_base : mh_base;
        const uint32_t b_base = vp ? mh_base : wh_base;

        float acc[4][4][4];
        #pragma unroll
        for (int i = 0; i < 4; i++)
            #pragma unroll
            for (int j = 0; j < 4; j++)
                #pragma unroll
                for (int r = 0; r < 4; r++) acc[i][j][r] = 0.f;

        #pragma unroll
        for (int k16 = 0; k16 < 4; k16++) {
            uint32_t af[4][4], bf[4][2];
            #pragma unroll
            for (int mt = 0; mt < 4; mt++) {
                uint32_t addr = a_base + a_lane + (uint32_t)(mt * 16 * 144 + k16 * 32);
                LDSM_X4(af[mt][0], af[mt][1], af[mt][2], af[mt][3], addr);
            }
            #pragma unroll
            for (int ntp = 0; ntp < 2; ntp++) {
                uint32_t addr = b_base + b_lane + (uint32_t)(ntp * 16 * 144 + k16 * 32);
                LDSM_X4(bf[2 * ntp][0], bf[2 * ntp][1], bf[2 * ntp + 1][0], bf[2 * ntp + 1][1], addr);
            }
            #pragma unroll
            for (int mt = 0; mt < 4; mt++)
                #pragma unroll
                for (int nt = 0; nt < 4; nt++)
                    MMA_F16(acc[mt][nt], af[mt], bf[nt]);
        }

        #pragma unroll
        for (int mt = 0; mt < 4; mt++) {
            #pragma unroll
            for (int half = 0; half < 2; half++) {
                int rloc = warp_m * 64 + mt * 16 + gid + half * 8;
                #pragma unroll
                for (int nt = 0; nt < 4; nt++) {
                    int cloc = warp_n * 32 + nt * 8 + tq * 2;
                    float c0 = acc[mt][nt][half * 2];
                    float c1 = acc[mt][nt][half * 2 + 1];
                    if (!vp) {
                        c0 = 1.f / (1.f + __expf(-c0));
                        c1 = 1.f / (1.f + __expf(-c1));
                    }
                    *(__half2*)&stage[rloc * STG + cloc] = __floats2half2_rn(c0, c1);
                }
            }
        }
        __syncthreads();

        if (vp) {
            #pragma unroll
            for (int t = 0; t < 8; t++) {
                int idx = tid + t * 256;
                int row = idx >> 4, c16 = idx & 15;
                int cglob = c4 * 128 + row;
                int hh = cglob >> 5, dd = cglob & 31;
                uint4 v = *(uint4*)&stage[row * STG + c16 * 8];
                *(uint4*)&d_vt[((size_t)hh * DCOL + ss * DCH + dd) * DN + jj0 + c16 * 8] = v;
            }
        } else {
            #pragma unroll
            for (int t = 0; t < 8; t++) {
                int idx = tid + t * 256;
                int row = idx >> 4, c16 = idx & 15;
                uint4 v = *(uint4*)&stage[row * STG + c16 * 8];
                *(uint4*)&d_gh[(size_t)(gr0 + row) * DHC + (c4 - 2) * 128 + c16 * 8] = v;
            }
        }
        __syncthreads();
    }
}

// ---------------------------------------------------------------------------
// K2 v2: unchanged (R13).
// ---------------------------------------------------------------------------
constexpr int K2ZS = 132;
constexpr int K2WS = 136;

__global__ void __launch_bounds__(256) k2_ln_bias_v2(const float* __restrict__ z,
                                                     const int* __restrict__ mask,
                                                     const float* __restrict__ nw,
                                                     const float* __restrict__ nb,
                                                     const float* __restrict__ Wz) {
    __shared__ __half zls[32 * K2ZS];
    __shared__ __half Wzh[8 * K2WS];
    __shared__ float nwS[128], nbS[128];

    const int tid = threadIdx.x;
    const int lane = tid & 31;
    const int wid = tid >> 5;
    const int sub = lane >> 3;
    const int li  = lane & 7;
    const int pl  = wid * 4 + sub;
    const size_t gp = (size_t)blockIdx.x * 32 + pl;

    if (tid < 128) { nwS[tid] = nw[tid]; nbS[tid] = nb[tid]; }
    {
        int n = tid >> 5, k = (tid & 31) * 4;
        float4 w4 = *(const float4*)&Wz[n * DCZ + k];
        *(__half2*)&Wzh[n * K2WS + k]     = __floats2half2_rn(w4.x, w4.y);
        *(__half2*)&Wzh[n * K2WS + k + 2] = __floats2half2_rn(w4.z, w4.w);
    }

    const float* zr = z + gp * DCZ + li * 16;
    float4 x[4];
    #pragma unroll
    for (int t = 0; t < 4; t++) x[t] = *(const float4*)&zr[t * 4];

    float s1 = 0.f, s2 = 0.f;
    #pragma unroll
    for (int t = 0; t < 4; t++) {
        s1 += x[t].x + x[t].y + x[t].z + x[t].w;
        s2 += x[t].x * x[t].x + x[t].y * x[t].y + x[t].z * x[t].z + x[t].w * x[t].w;
    }
    #pragma unroll
    for (int off = 4; off; off >>= 1) {
        s1 += __shfl_xor_sync(0xffffffffu, s1, off);
        s2 += __shfl_xor_sync(0xffffffffu, s2, off);
    }
    float mu  = s1 * (1.f / 128.f);
    float inv = rsqrtf(s2 * (1.f / 128.f) - mu * mu + 1e-5f);
    __syncthreads();

    {
        const float* xp = (const float*)x;
        #pragma unroll
        for (int c = 0; c < 16; c += 2) {
            int ch = li * 16 + c;
            float v0 = (xp[c]     - mu) * inv * nwS[ch]     + nbS[ch];
            float v1 = (xp[c + 1] - mu) * inv * nwS[ch + 1] + nbS[ch + 1];
            *(__half2*)&zls[pl * K2ZS + ch] = __floats2half2_rn(v0, v1);
        }
    }
    __syncthreads();

    if (wid < 2) {
        const int pb = wid * 16;
        const int gid = lane >> 2, tq = lane & 3;
        float acc[4] = {0.f, 0.f, 0.f, 0.f};
        #pragma unroll
        for (int k16 = 0; k16 < 8; k16++) {
            uint32_t af[4], bf[2];
            af[0] = *(const uint32_t*)&zls[(pb + gid) * K2ZS + k16 * 16 + tq * 2];
            af[1] = *(const uint32_t*)&zls[(pb + gid + 8) * K2ZS + k16 * 16 + tq * 2];
            af[2] = *(const uint32_t*)&zls[(pb + gid) * K2ZS + k16 * 16 + tq * 2 + 8];
            af[3] = *(const uint32_t*)&zls[(pb + gid + 8) * K2ZS + k16 * 16 + tq * 2 + 8];
            bf[0] = *(const uint32_t*)&Wzh[gid * K2WS + k16 * 16 + tq * 2];
            bf[1] = *(const uint32_t*)&Wzh[gid * K2WS + k16 * 16 + tq * 2 + 8];
            MMA_F16(acc, af, bf);
        }
        size_t gp0 = (size_t)blockIdx.x * 32 + pb + gid;
        float pen0 = (mask[gp0] != 0) ? 0.f : -1e6f;
        float pen1 = (mask[gp0 + 8] != 0) ? 0.f : -1e6f;
        d_b[(size_t)(tq * 2)     * DNN + gp0]     = acc[0] + pen0;
        d_b[(size_t)(tq * 2 + 1) * DNN + gp0]     = acc[1] + pen0;
        d_b[(size_t)(tq * 2)     * DNN + gp0 + 8] = acc[2] + pen1;
        d_b[(size_t)(tq * 2 + 1) * DNN + gp0 + 8] = acc[3] + pen1;
    }
}

// ---------------------------------------------------------------------------
// K3: softmax. Unchanged (R13).
// ---------------------------------------------------------------------------
__global__ void k3_softmax() {
    __shared__ float sd[256];
    const float* p = d_b + (size_t)blockIdx.x * DN;
    __half* q = d_bh + (size_t)blockIdx.x * DN;
    int tid = threadIdx.x;
    float x0 = p[tid], x1 = p[tid + 256], x2 = p[tid + 512];
    float mx = fmaxf(x0, fmaxf(x1, x2));
    sd[tid] = mx; __syncthreads();
    #pragma unroll
    for (int s = 128; s; s >>= 1) {
        if (tid < s) sd[tid] = fmaxf(sd[tid], sd[tid + s]);
        __syncthreads();
    }
    float bm = sd[0]; __syncthreads();
    float e0 = __expf(x0 - bm), e1 = __expf(x1 - bm), e2 = __expf(x2 - bm);
    sd[tid] = e0 + e1 + e2; __syncthreads();
    #pragma unroll
    for (int s = 128; s; s >>= 1) {
        if (tid < s) sd[tid] += sd[tid + s];
        __syncthreads();
    }
    float invs = 1.f / sd[0];
    q[tid]       = __float2half_rn(e0 * invs);
    q[tid + 256] = __float2half_rn(e1 * invs);
    q[tid + 512] = __float2half_rn(e2 * invs);
}

// ---------------------------------------------------------------------------
// K4 v7: block 128x256, warp tile 64x64, k32 double-buffered via cp.async.
// Staging flows global->smem without register round-trips; copies overlap MMA.
// ---------------------------------------------------------------------------
constexpr int K4ST = 40;                 // halfs per staged row
constexpr int K4AB = 128 * K4ST;         // A buffer (halfs)
constexpr int K4BB = 256 * K4ST;         // B buffer (halfs)
constexpr int K4STG = 264;               // epilogue stage stride (halfs)
constexpr int K4_SMEM = 128 * K4STG * 2; // 67584 B (>= 61440 mainloop)

__global__ void __launch_bounds__(256) k4_gemm_fp16_v7() {
    extern __shared__ __half sall[];
    const int h = blockIdx.z;
    const __half* A = d_bh + (size_t)h * DNN;
    const __half* B = d_vt + (size_t)h * DCOL * DN;
    __half* C = d_oh + (size_t)h * DN * DCOL;
    const int bm0 = blockIdx.y * 128;
    const int bn0 = blockIdx.x * 256;
    const int tid = threadIdx.x;
    const int lane = tid & 31;
    const int wid = tid >> 5;
    const int warp_m = wid >> 2;       // 0..1 -> 64 rows
    const int warp_n = wid & 3;        // 0..3 -> 64 cols
    const int gid = lane >> 2;
    const int tq  = lane & 3;

    const int ra = tid >> 1;           // A row 0..127
    const int sela = tid & 1;

    __half* Abuf = sall;                         // [2][128][40]
    __half* Bbuf = sall + 2 * K4AB;              // [2][256][40]
    const uint32_t as_base = smem_u32(Abuf);
    const uint32_t bs_base = smem_u32(Bbuf);
    const uint32_t a_lane = (uint32_t)((warp_m * 64 + (lane & 15)) * 80 + (lane >> 4) * 16);
    const uint32_t b_lane = (uint32_t)((warp_n * 64 + (lane & 7) + ((lane >> 4) & 1) * 8) * 80
                                       + ((lane >> 3) & 1) * 16);
    constexpr uint32_t ABUFB = K4AB * 2;   // bytes per A buffer
    constexpr uint32_t BBUFB = K4BB * 2;   // bytes per B buffer

    // per-thread staging destinations (byte offsets within a buffer)
    const uint32_t a_dst0 = (uint32_t)((ra * K4ST + sela * 8) * 2);
    const uint32_t a_dst1 = a_dst0 + 32;                 // +16 halfs

    float acc[4][8][4];
    #pragma unroll
    for (int i = 0; i < 4; i++)
        #pragma unroll
        for (int j = 0; j < 8; j++)
            #pragma unroll
            for (int rr = 0; rr < 4; rr++) acc[i][j][rr] = 0.f;

    // stage tile 0 (k = 0..31) via cp.async
    {
        CP_ASYNC16(as_base + a_dst0, &A[(size_t)(bm0 + ra) * DN + sela * 8]);
        CP_ASYNC16(as_base + a_dst1, &A[(size_t)(bm0 + ra) * DN + 16 + sela * 8]);
        #pragma unroll
        for (int t = 0; t < 4; t++) {
            int idx = tid + t * 256;              // 0..1023
            int row = idx >> 2, q = idx & 3;
            CP_ASYNC16(bs_base + (uint32_t)((row * K4ST + q * 8) * 2),
                       &B[(size_t)(bn0 + row) * DN + q * 8]);
        }
        CP_COMMIT();
        CP_WAIT0();
    }
    __syncthreads();

    for (int c = 0; c < 24; c++) {
        const int cur = c & 1;
        const bool more = (c + 1 < 24);

        // issue next-stage copies first so they overlap the MMA block
        if (more) {
            int kn = (c + 1) * 32;
            uint32_t ab = as_base + (cur ^ 1) * ABUFB;
            uint32_t bb = bs_base + (cur ^ 1) * BBUFB;
            CP_ASYNC16(ab + a_dst0, &A[(size_t)(bm0 + ra) * DN + kn + sela * 8]);
            CP_ASYNC16(ab + a_dst1, &A[(size_t)(bm0 + ra) * DN + kn + 16 + sela * 8]);
            #pragma unroll
            for (int t = 0; t < 4; t++) {
                int idx = tid + t * 256;
                int row = idx >> 2, q = idx & 3;
                CP_ASYNC16(bb + (uint32_t)((row * K4ST + q * 8) * 2),
                           &B[(size_t)(bn0 + row) * DN + kn + q * 8]);
            }
            CP_COMMIT();
        }

        #pragma unroll
        for (int k16 = 0; k16 < 2; k16++) {
            uint32_t af[4][4], bf[8][2];
            #pragma unroll
            for (int mt = 0; mt < 4; mt++) {
                uint32_t addr = as_base + cur * ABUFB + a_lane
                              + (uint32_t)(mt * 16 * 80 + k16 * 32);
                LDSM_X4(af[mt][0], af[mt][1], af[mt][2], af[mt][3], addr);
            }
            #pragma unroll
            for (int ntp = 0; ntp < 4; ntp++) {
                uint32_t addr = bs_base + cur * BBUFB + b_lane
                              + (uint32_t)(ntp * 16 * 80 + k16 * 32);
                LDSM_X4(bf[2 * ntp][0], bf[2 * ntp][1], bf[2 * ntp + 1][0], bf[2 * ntp + 1][1], addr);
            }
            #pragma unroll
            for (int mt = 0; mt < 4; mt++)
                #pragma unroll
                for (int nt = 0; nt < 8; nt++)
                    MMA_F16(acc[mt][nt], af[mt], bf[nt]);
        }

        if (more) CP_WAIT0();
        __syncthreads();
    }

    // staged coalesced epilogue: stage [128][264] halfs (reuses sall)
    __half* stage = sall;
    #pragma unroll
    for (int mt = 0; mt < 4; mt++) {
        #pragma unroll
        for (int half = 0; half < 2; half++) {
            int rloc = warp_m * 64 + mt * 16 + gid + half * 8;
            #pragma unroll
            for (int nt = 0; nt < 8; nt++) {
                int cloc = warp_n * 64 + nt * 8 + tq * 2;
                *(__half2*)&stage[rloc * K4STG + cloc] =
                    __floats2half2_rn(acc[mt][nt][half * 2], acc[mt][nt][half * 2 + 1]);
            }
        }
    }
    __syncthreads();
    #pragma unroll
    for (int t = 0; t < 16; t++) {
        int idx = tid + t * 256;          // 0..4095
        int row = idx >> 5, c32 = idx & 31;
        uint4 v = *(uint4*)&stage[row * K4STG + c32 * 8];
        *(uint4*)&C[(size_t)(bm0 + row) * DCOL + bn0 + c32 * 8] = v;
    }
}

// ---------------------------------------------------------------------------
// K5 (fp16 mma): unchanged (R13).
// ---------------------------------------------------------------------------
constexpr int K5ST = 72;
constexpr int K5_SMEM = (128 * K5ST + 64 * K5ST) * 2;

__global__ void k5_out_fp16(float* __restrict__ out) {
    extern __shared__ __half sm5h[];
    __half* As = sm5h;
    __half* Bs = As + 128 * K5ST;

    const int tid = threadIdx.x;
    const int gr0 = blockIdx.x * 128;
    const int ss = gr0 / DN;
    const int i0 = gr0 - ss * DN;

    const int lane = tid & 31;
    const int wid  = tid >> 5;
    const int warp_m = wid >> 1;
    const int warp_n = wid & 1;
    const int gid = lane >> 2;
    const int tq  = lane & 3;

    float acc[2][4][4];
    #pragma unroll
    for (int i = 0; i < 2; i++)
        #pragma unroll
        for (int j = 0; j < 4; j++)
            #pragma unroll
            for (int r = 0; r < 4; r++) acc[i][j][r] = 0.f;

    for (int ck0 = 0; ck0 < DHC; ck0 += 64) {
        #pragma unroll
        for (int t = 0; t < 2; t++) {
            int idx = tid + t * 256;
            int n = idx >> 3, c8 = (idx & 7) * 8;
            *(uint4*)&Bs[n * K5ST + c8] = *(const uint4*)&d_woh[n * DHC + ck0 + c8];
        }
        #pragma unroll
        for (int t = 0; t < 16; t++) {
            int idx = tid + t * 256;
            int r = idx >> 5;
            int cl = (idx & 31) * 2;
            int c = ck0 + cl;
            int h = c >> 5, d = c & 31;
            __half2 ov = *(const __half2*)&d_oh[((size_t)(h * DN + i0 + r) * DS + ss) * DCH + d];
            __half2 gv = *(const __half2*)&d_gh[(size_t)(gr0 + r) * DHC + c];
            float2 of = __half22float2(ov);
            float2 gf = __half22float2(gv);
            *(__half2*)&As[r * K5ST + cl] =
                __floats2half2_rn(gf.x * of.x, gf.y * of.y);
        }
        __syncthreads();

        #pragma unroll
        for (int k16 = 0; k16 < 4; k16++) {
            uint32_t af[2][4], bf[4][2];
            #pragma unroll
            for (int mt = 0; mt < 2; mt++) {
                int row = warp_m * 32 + mt * 16 + gid;
                af[mt][0] = *(const uint32_t*)&As[row * K5ST + k16 * 16 + tq * 2];
                af[mt][1] = *(const uint32_t*)&As[(row + 8) * K5ST + k16 * 16 + tq * 2];
                af[mt][2] = *(const uint32_t*)&As[row * K5ST + k16 * 16 + tq * 2 + 8];
                af[mt][3] = *(const uint32_t*)&As[(row + 8) * K5ST + k16 * 16 + tq * 2 + 8];
            }
            #pragma unroll
            for (int nt = 0; nt < 4; nt++) {
                int col = warp_n * 32 + nt * 8 + gid;
                bf[nt][0] = *(const uint32_t*)&Bs[col * K5ST + k16 * 16 + tq * 2];
                bf[nt][1] = *(const uint32_t*)&Bs[col * K5ST + k16 * 16 + tq * 2 + 8];
            }
            #pragma unroll
            for (int mt = 0; mt < 2; mt++)
                #pragma unroll
                for (int nt = 0; nt < 4; nt++)
                    MMA_F16(acc[mt][nt], af[mt], bf[nt]);
        }
        __syncthreads();
    }

    #pragma unroll
    for (int mt = 0; mt < 2; mt++) {
        #pragma unroll
        for (int nt = 0; nt < 4; nt++) {
            int row = gr0 + warp_m * 32 + mt * 16 + gid;
            int col = warp_n * 32 + nt * 8 + tq * 2;
            *(float2*)&out[(size_t)row * DCM + col] =
                make_float2(acc[mt][nt][0], acc[mt][nt][1]);
            *(float2*)&out[(size_t)(row + 8) * DCM + col] =
                make_float2(acc[mt][nt][2], acc[mt][nt][3]);
        }
    }
}

// ---------------------------------------------------------------------------
extern "C" void kernel_launch(void* const* d_in, const int* in_sizes, int n_in,
                              void* d_out, int out_size) {
    const float* m    = (const float*)d_in[0];
    const float* z    = (const float*)d_in[1];
    const int*   mask = (const int*)d_in[2];
    const float* nmw  = (const float*)d_in[3];
    const float* nmb  = (const float*)d_in[4];
    const float* nzw  = (const float*)d_in[5];
    const float* nzb  = (const float*)d_in[6];
    const float* Wm   = (const float*)d_in[7];
    const float* Wg   = (const float*)d_in[8];
    const float* Wz   = (const float*)d_in[9];
    const float* Wo   = (const float*)d_in[10];
    float* out = (float*)d_out;

    cudaFuncSetAttribute(k1_ln_vg_v3,     cudaFuncAttributeMaxDynamicSharedMemorySize, K1_SMEM);
    cudaFuncSetAttribute(k4_gemm_fp16_v7, cudaFuncAttributeMaxDynamicSharedMemorySize, K4_SMEM);
    cudaFuncSetAttribute(k5_out_fp16,     cudaFuncAttributeMaxDynamicSharedMemorySize, K5_SMEM);

    k0_convert_w<<<64, 256>>>(Wm, Wg, Wo);
    k1_ln_vg_v3<<<DSN / 128, 256, K1_SMEM>>>(m, nmw, nmb);
    k2_ln_bias_v2<<<DNN / 32, 256>>>(z, mask, nzw, nzb, Wz);
    k3_softmax<<<DH * DN, 256>>>();
    dim3 g4(DCOL / 256, DN / 128, DH);
    k4_gemm_fp16_v7<<<g4, 256, K4_SMEM>>>();
    k5_out_fp16<<<DSN / 128, 256, K5_SMEM>>>(out);
}

// round 17
// speedup vs baseline: 1.1429x; 1.0279x over previous
#include <cuda_runtime.h>
#include <cuda_fp16.h>
#include <math.h>
#include <stdint.h>

// Dims
constexpr int DS  = 256;   // S
constexpr int DN  = 768;   // N
constexpr int DCM = 64;    // CM
constexpr int DCZ = 128;   // CZ
constexpr int DH  = 8;     // heads
constexpr int DCH = 32;    // per-head channels
constexpr int DHC = 256;   // H*CH
constexpr int DSN = DS * DN;          // 196608 rows of m
constexpr int DNN = DN * DN;          // 589824 pairs
constexpr int DCOL = DS * DCH;        // 8192 GEMM cols

// Scratch (device globals; no allocations allowed)
__device__ __half d_vt[(size_t)DH * DCOL * DN];  // v^T fp16: [h][n=s*32+d][j]
__device__ __half d_bh[(size_t)DH * DNN];        // softmax probs fp16: [h][i][j]
__device__ __half d_gh[(size_t)DSN * DHC];       // gate fp16: [s*N+j][hc]
__device__ float  d_b[(size_t)DH * DNN];         // logits f32 (K2 -> K3)
__device__ __half d_oh[(size_t)DN * DS * DHC];   // gated o fp16: [i][s][h*32+d]
__device__ __half d_wmh[DHC * DCM];              // Wm fp16
__device__ __half d_wgh[DHC * DCM];              // Wg fp16
__device__ __half d_woh[DCM * DHC];              // Wo fp16

__device__ __forceinline__ uint32_t smem_u32(const void* p) {
    uint32_t a;
    asm("{ .reg .u64 t; cvta.to.shared.u64 t, %1; cvt.u32.u64 %0, t; }"
        : "=r"(a) : "l"(p));
    return a;
}

#define MMA_F16(acc, af, bf)                                                  \
    asm volatile(                                                             \
        "mma.sync.aligned.m16n8k16.row.col.f32.f16.f16.f32 "                  \
        "{%0,%1,%2,%3}, {%4,%5,%6,%7}, {%8,%9}, {%0,%1,%2,%3};"               \
        : "+f"((acc)[0]), "+f"((acc)[1]), "+f"((acc)[2]), "+f"((acc)[3])      \
        : "r"((af)[0]), "r"((af)[1]), "r"((af)[2]), "r"((af)[3]),             \
          "r"((bf)[0]), "r"((bf)[1]))

#define LDSM_X4(r0, r1, r2, r3, addr)                                         \
    asm volatile("ldmatrix.sync.aligned.m8n8.x4.shared.b16 {%0,%1,%2,%3}, [%4];" \
        : "=r"(r0), "=r"(r1), "=r"(r2), "=r"(r3) : "r"(addr))

#define CP_ASYNC16(dst, src)                                                  \
    asm volatile("cp.async.cg.shared.global [%0], [%1], 16;"                  \
        :: "r"(dst), "l"(src) : "memory")
#define CP_COMMIT() asm volatile("cp.async.commit_group;" ::: "memory")
#define CP_WAIT0()  asm volatile("cp.async.wait_group 0;" ::: "memory")

constexpr int STG = 136;   // K1 staged-epilogue stride (halfs)

// ---------------------------------------------------------------------------
// K0: one-time weight conversion f32 -> fp16 (Wm, Wg, Wo). Grid 64 x 256.
// ---------------------------------------------------------------------------
__global__ void k0_convert_w(const float* __restrict__ Wm,
                             const float* __restrict__ Wg,
                             const float* __restrict__ Wo) {
    int idx = blockIdx.x * 256 + threadIdx.x;   // 0..16383
    d_wmh[idx] = __float2half_rn(Wm[idx]);
    d_wgh[idx] = __float2half_rn(Wg[idx]);
    d_woh[idx] = __float2half_rn(Wo[idx]);
}

// ---------------------------------------------------------------------------
// K1 v3 (fp16 mma, single pass, coalesced staged epilogue). Unchanged (R13).
// ---------------------------------------------------------------------------
constexpr int K1MH = 72;
constexpr int K1_SMEM = 128 * 68 * 4 + 2 * (128 * K1MH * 2) + 128 * 4;  // 72192

__global__ void __launch_bounds__(256) k1_ln_vg_v3(const float* __restrict__ m,
                                                   const float* __restrict__ nw,
                                                   const float* __restrict__ nb) {
    extern __shared__ char sm1raw[];
    float*  As  = (float*)sm1raw;                                    // [128][68]
    __half* mh  = (__half*)(sm1raw + 128 * 68 * 4);                  // [128][72]
    __half* Wh  = (__half*)(sm1raw + 128 * 68 * 4 + 128 * K1MH * 2); // [128][72]
    float*  snw = (float*)(sm1raw + 128 * 68 * 4 + 2 * 128 * K1MH * 2);
    float*  snb = snw + 64;
    __half* stage = (__half*)sm1raw;   // reuse As region after LN: [128][136]

    const int tid = threadIdx.x;
    const int gr0 = blockIdx.x * 128;

    #pragma unroll
    for (int t = 0; t < 8; t++) {
        int f = tid + t * 256;
        int r = f >> 4;
        int k = (f & 15) << 2;
        float4 v4 = *(const float4*)&m[(size_t)(gr0 + r) * DCM + k];
        *(float4*)&As[r * 68 + k] = v4;
    }
    if (tid < 64) { snw[tid] = nw[tid]; snb[tid] = nb[tid]; }
    __syncthreads();

    if (tid < 128) {
        float s1 = 0.f, s2 = 0.f;
        #pragma unroll
        for (int k = 0; k < 64; k++) {
            float x = As[tid * 68 + k];
            s1 += x; s2 += x * x;
        }
        float mu  = s1 * (1.f / 64.f);
        float var = s2 * (1.f / 64.f) - mu * mu;
        float inv = rsqrtf(var + 1e-5f);
        #pragma unroll
        for (int k = 0; k < 64; k += 2) {
            float x0 = (As[tid * 68 + k]     - mu) * inv * snw[k]     + snb[k];
            float x1 = (As[tid * 68 + k + 1] - mu) * inv * snw[k + 1] + snb[k + 1];
            *(__half2*)&mh[tid * K1MH + k] = __floats2half2_rn(x0, x1);
        }
    }
    __syncthreads();

    const int lane = tid & 31;
    const int wid  = tid >> 5;
    const int warp_m = wid >> 2;
    const int warp_n = wid & 3;
    const int gid = lane >> 2;
    const int tq  = lane & 3;

    const uint32_t mh_base = smem_u32(mh);
    const uint32_t wh_base = smem_u32(Wh);
    const uint32_t a_lane = (uint32_t)((warp_m * 64 + (lane & 15)) * 144 + (lane >> 4) * 16);
    const uint32_t b_lane = (uint32_t)((warp_n * 32 + (lane & 7) + ((lane >> 4) & 1) * 8) * 144
                                       + ((lane >> 3) & 1) * 16);

    const int ss = gr0 / DN;
    const int jj0 = gr0 - ss * DN;

    for (int c4 = 0; c4 < 4; c4++) {
        const bool vp = (c4 < 2);
        const __half* Wsrc = vp ? (d_wmh + (size_t)(c4 * 128) * DCM)
                                : (d_wgh + (size_t)((c4 - 2) * 128) * DCM);
        #pragma unroll
        for (int t = 0; t < 4; t++) {
            int idx = tid + t * 256;
            int n = idx >> 3, c8 = (idx & 7) * 8;
            *(uint4*)&Wh[n * K1MH + c8] = *(const uint4*)&Wsrc[n * DCM + c8];
        }
        __syncthreads();

        const uint32_t a_base = vp ? wh_base : mh_base;
        const uint32_t b_base = vp ? mh_base : wh_base;

        float acc[4][4][4];
        #pragma unroll
        for (int i = 0; i < 4; i++)
            #pragma unroll
            for (int j = 0; j < 4; j++)
                #pragma unroll
                for (int r = 0; r < 4; r++) acc[i][j][r] = 0.f;

        #pragma unroll
        for (int k16 = 0; k16 < 4; k16++) {
            uint32_t af[4][4], bf[4][2];
            #pragma unroll
            for (int mt = 0; mt < 4; mt++) {
                uint32_t addr = a_base + a_lane + (uint32_t)(mt * 16 * 144 + k16 * 32);
                LDSM_X4(af[mt][0], af[mt][1], af[mt][2], af[mt][3], addr);
            }
            #pragma unroll
            for (int ntp = 0; ntp < 2; ntp++) {
                uint32_t addr = b_base + b_lane + (uint32_t)(ntp * 16 * 144 + k16 * 32);
                LDSM_X4(bf[2 * ntp][0], bf[2 * ntp][1], bf[2 * ntp + 1][0], bf[2 * ntp + 1][1], addr);
            }
            #pragma unroll
            for (int mt = 0; mt < 4; mt++)
                #pragma unroll
                for (int nt = 0; nt < 4; nt++)
                    MMA_F16(acc[mt][nt], af[mt], bf[nt]);
        }

        #pragma unroll
        for (int mt = 0; mt < 4; mt++) {
            #pragma unroll
            for (int half = 0; half < 2; half++) {
                int rloc = warp_m * 64 + mt * 16 + gid + half * 8;
                #pragma unroll
                for (int nt = 0; nt < 4; nt++) {
                    int cloc = warp_n * 32 + nt * 8 + tq * 2;
                    float c0 = acc[mt][nt][half * 2];
                    float c1 = acc[mt][nt][half * 2 + 1];
                    if (!vp) {
                        c0 = 1.f / (1.f + __expf(-c0));
                        c1 = 1.f / (1.f + __expf(-c1));
                    }
                    *(__half2*)&stage[rloc * STG + cloc] = __floats2half2_rn(c0, c1);
                }
            }
        }
        __syncthreads();

        if (vp) {
            #pragma unroll
            for (int t = 0; t < 8; t++) {
                int idx = tid + t * 256;
                int row = idx >> 4, c16 = idx & 15;
                int cglob = c4 * 128 + row;
                int hh = cglob >> 5, dd = cglob & 31;
                uint4 v = *(uint4*)&stage[row * STG + c16 * 8];
                *(uint4*)&d_vt[((size_t)hh * DCOL + ss * DCH + dd) * DN + jj0 + c16 * 8] = v;
            }
        } else {
            #pragma unroll
            for (int t = 0; t < 8; t++) {
                int idx = tid + t * 256;
                int row = idx >> 4, c16 = idx & 15;
                uint4 v = *(uint4*)&stage[row * STG + c16 * 8];
                *(uint4*)&d_gh[(size_t)(gr0 + row) * DHC + (c4 - 2) * 128 + c16 * 8] = v;
            }
        }
        __syncthreads();
    }
}

// ---------------------------------------------------------------------------
// K2 v2: unchanged (R13).
// ---------------------------------------------------------------------------
constexpr int K2ZS = 132;
constexpr int K2WS = 136;

__global__ void __launch_bounds__(256) k2_ln_bias_v2(const float* __restrict__ z,
                                                     const int* __restrict__ mask,
                                                     const float* __restrict__ nw,
                                                     const float* __restrict__ nb,
                                                     const float* __restrict__ Wz) {
    __shared__ __half zls[32 * K2ZS];
    __shared__ __half Wzh[8 * K2WS];
    __shared__ float nwS[128], nbS[128];

    const int tid = threadIdx.x;
    const int lane = tid & 31;
    const int wid = tid >> 5;
    const int sub = lane >> 3;
    const int li  = lane & 7;
    const int pl  = wid * 4 + sub;
    const size_t gp = (size_t)blockIdx.x * 32 + pl;

    if (tid < 128) { nwS[tid] = nw[tid]; nbS[tid] = nb[tid]; }
    {
        int n = tid >> 5, k = (tid & 31) * 4;
        float4 w4 = *(const float4*)&Wz[n * DCZ + k];
        *(__half2*)&Wzh[n * K2WS + k]     = __floats2half2_rn(w4.x, w4.y);
        *(__half2*)&Wzh[n * K2WS + k + 2] = __floats2half2_rn(w4.z, w4.w);
    }

    const float* zr = z + gp * DCZ + li * 16;
    float4 x[4];
    #pragma unroll
    for (int t = 0; t < 4; t++) x[t] = *(const float4*)&zr[t * 4];

    float s1 = 0.f, s2 = 0.f;
    #pragma unroll
    for (int t = 0; t < 4; t++) {
        s1 += x[t].x + x[t].y + x[t].z + x[t].w;
        s2 += x[t].x * x[t].x + x[t].y * x[t].y + x[t].z * x[t].z + x[t].w * x[t].w;
    }
    #pragma unroll
    for (int off = 4; off; off >>= 1) {
        s1 += __shfl_xor_sync(0xffffffffu, s1, off);
        s2 += __shfl_xor_sync(0xffffffffu, s2, off);
    }
    float mu  = s1 * (1.f / 128.f);
    float inv = rsqrtf(s2 * (1.f / 128.f) - mu * mu + 1e-5f);
    __syncthreads();

    {
        const float* xp = (const float*)x;
        #pragma unroll
        for (int c = 0; c < 16; c += 2) {
            int ch = li * 16 + c;
            float v0 = (xp[c]     - mu) * inv * nwS[ch]     + nbS[ch];
            float v1 = (xp[c + 1] - mu) * inv * nwS[ch + 1] + nbS[ch + 1];
            *(__half2*)&zls[pl * K2ZS + ch] = __floats2half2_rn(v0, v1);
        }
    }
    __syncthreads();

    if (wid < 2) {
        const int pb = wid * 16;
        const int gid = lane >> 2, tq = lane & 3;
        float acc[4] = {0.f, 0.f, 0.f, 0.f};
        #pragma unroll
        for (int k16 = 0; k16 < 8; k16++) {
            uint32_t af[4], bf[2];
            af[0] = *(const uint32_t*)&zls[(pb + gid) * K2ZS + k16 * 16 + tq * 2];
            af[1] = *(const uint32_t*)&zls[(pb + gid + 8) * K2ZS + k16 * 16 + tq * 2];
            af[2] = *(const uint32_t*)&zls[(pb + gid) * K2ZS + k16 * 16 + tq * 2 + 8];
            af[3] = *(const uint32_t*)&zls[(pb + gid + 8) * K2ZS + k16 * 16 + tq * 2 + 8];
            bf[0] = *(const uint32_t*)&Wzh[gid * K2WS + k16 * 16 + tq * 2];
            bf[1] = *(const uint32_t*)&Wzh[gid * K2WS + k16 * 16 + tq * 2 + 8];
            MMA_F16(acc, af, bf);
        }
        size_t gp0 = (size_t)blockIdx.x * 32 + pb + gid;
        float pen0 = (mask[gp0] != 0) ? 0.f : -1e6f;
        float pen1 = (mask[gp0 + 8] != 0) ? 0.f : -1e6f;
        d_b[(size_t)(tq * 2)     * DNN + gp0]     = acc[0] + pen0;
        d_b[(size_t)(tq * 2 + 1) * DNN + gp0]     = acc[1] + pen0;
        d_b[(size_t)(tq * 2)     * DNN + gp0 + 8] = acc[2] + pen1;
        d_b[(size_t)(tq * 2 + 1) * DNN + gp0 + 8] = acc[3] + pen1;
    }
}

// ---------------------------------------------------------------------------
// K3: softmax. Unchanged (R13).
// ---------------------------------------------------------------------------
__global__ void k3_softmax() {
    __shared__ float sd[256];
    const float* p = d_b + (size_t)blockIdx.x * DN;
    __half* q = d_bh + (size_t)blockIdx.x * DN;
    int tid = threadIdx.x;
    float x0 = p[tid], x1 = p[tid + 256], x2 = p[tid + 512];
    float mx = fmaxf(x0, fmaxf(x1, x2));
    sd[tid] = mx; __syncthreads();
    #pragma unroll
    for (int s = 128; s; s >>= 1) {
        if (tid < s) sd[tid] = fmaxf(sd[tid], sd[tid + s]);
        __syncthreads();
    }
    float bm = sd[0]; __syncthreads();
    float e0 = __expf(x0 - bm), e1 = __expf(x1 - bm), e2 = __expf(x2 - bm);
    sd[tid] = e0 + e1 + e2; __syncthreads();
    #pragma unroll
    for (int s = 128; s; s >>= 1) {
        if (tid < s) sd[tid] += sd[tid + s];
        __syncthreads();
    }
    float invs = 1.f / sd[0];
    q[tid]       = __float2half_rn(e0 * invs);
    q[tid + 256] = __float2half_rn(e1 * invs);
    q[tid + 512] = __float2half_rn(e2 * invs);
}

// ---------------------------------------------------------------------------
// K4 v8: block 128x256, warp tile 64x64, k32 cp.async double-buffered.
// Epilogue applies the gate and writes gated o to [i][s][h*32+d] layout.
// ---------------------------------------------------------------------------
constexpr int K4ST = 40;                 // halfs per staged row
constexpr int K4AB = 128 * K4ST;         // A buffer (halfs)
constexpr int K4BB = 256 * K4ST;         // B buffer (halfs)
constexpr int K4STG = 264;               // epilogue stage stride (halfs)
constexpr int K4_SMEM = 128 * K4STG * 2; // 67584 B (>= 61440 mainloop)

__global__ void __launch_bounds__(256) k4_gemm_fp16_v8() {
    extern __shared__ __half sall[];
    const int h = blockIdx.z;
    const __half* A = d_bh + (size_t)h * DNN;
    const __half* B = d_vt + (size_t)h * DCOL * DN;
    const int bm0 = blockIdx.y * 128;
    const int bn0 = blockIdx.x * 256;
    const int tid = threadIdx.x;
    const int lane = tid & 31;
    const int wid = tid >> 5;
    const int warp_m = wid >> 2;
    const int warp_n = wid & 3;
    const int gid = lane >> 2;
    const int tq  = lane & 3;

    const int ra = tid >> 1;
    const int sela = tid & 1;

    __half* Abuf = sall;                         // [2][128][40]
    __half* Bbuf = sall + 2 * K4AB;              // [2][256][40]
    const uint32_t as_base = smem_u32(Abuf);
    const uint32_t bs_base = smem_u32(Bbuf);
    const uint32_t a_lane = (uint32_t)((warp_m * 64 + (lane & 15)) * 80 + (lane >> 4) * 16);
    const uint32_t b_lane = (uint32_t)((warp_n * 64 + (lane & 7) + ((lane >> 4) & 1) * 8) * 80
                                       + ((lane >> 3) & 1) * 16);
    constexpr uint32_t ABUFB = K4AB * 2;
    constexpr uint32_t BBUFB = K4BB * 2;

    const uint32_t a_dst0 = (uint32_t)((ra * K4ST + sela * 8) * 2);
    const uint32_t a_dst1 = a_dst0 + 32;

    float acc[4][8][4];
    #pragma unroll
    for (int i = 0; i < 4; i++)
        #pragma unroll
        for (int j = 0; j < 8; j++)
            #pragma unroll
            for (int rr = 0; rr < 4; rr++) acc[i][j][rr] = 0.f;

    {
        CP_ASYNC16(as_base + a_dst0, &A[(size_t)(bm0 + ra) * DN + sela * 8]);
        CP_ASYNC16(as_base + a_dst1, &A[(size_t)(bm0 + ra) * DN + 16 + sela * 8]);
        #pragma unroll
        for (int t = 0; t < 4; t++) {
            int idx = tid + t * 256;
            int row = idx >> 2, q = idx & 3;
            CP_ASYNC16(bs_base + (uint32_t)((row * K4ST + q * 8) * 2),
                       &B[(size_t)(bn0 + row) * DN + q * 8]);
        }
        CP_COMMIT();
        CP_WAIT0();
    }
    __syncthreads();

    for (int c = 0; c < 24; c++) {
        const int cur = c & 1;
        const bool more = (c + 1 < 24);

        if (more) {
            int kn = (c + 1) * 32;
            uint32_t ab = as_base + (cur ^ 1) * ABUFB;
            uint32_t bb = bs_base + (cur ^ 1) * BBUFB;
            CP_ASYNC16(ab + a_dst0, &A[(size_t)(bm0 + ra) * DN + kn + sela * 8]);
            CP_ASYNC16(ab + a_dst1, &A[(size_t)(bm0 + ra) * DN + kn + 16 + sela * 8]);
            #pragma unroll
            for (int t = 0; t < 4; t++) {
                int idx = tid + t * 256;
                int row = idx >> 2, q = idx & 3;
                CP_ASYNC16(bb + (uint32_t)((row * K4ST + q * 8) * 2),
                           &B[(size_t)(bn0 + row) * DN + kn + q * 8]);
            }
            CP_COMMIT();
        }

        #pragma unroll
        for (int k16 = 0; k16 < 2; k16++) {
            uint32_t af[4][4], bf[8][2];
            #pragma unroll
            for (int mt = 0; mt < 4; mt++) {
                uint32_t addr = as_base + cur * ABUFB + a_lane
                              + (uint32_t)(mt * 16 * 80 + k16 * 32);
                LDSM_X4(af[mt][0], af[mt][1], af[mt][2], af[mt][3], addr);
            }
            #pragma unroll
            for (int ntp = 0; ntp < 4; ntp++) {
                uint32_t addr = bs_base + cur * BBUFB + b_lane
                              + (uint32_t)(ntp * 16 * 80 + k16 * 32);
                LDSM_X4(bf[2 * ntp][0], bf[2 * ntp][1], bf[2 * ntp + 1][0], bf[2 * ntp + 1][1], addr);
            }
            #pragma unroll
            for (int mt = 0; mt < 4; mt++)
                #pragma unroll
                for (int nt = 0; nt < 8; nt++)
                    MMA_F16(acc[mt][nt], af[mt], bf[nt]);
        }

        if (more) CP_WAIT0();
        __syncthreads();
    }

    // staged epilogue: gate-multiply + write to [i][s][h*32+d] layout
    __half* stage = sall;
    #pragma unroll
    for (int mt = 0; mt < 4; mt++) {
        #pragma unroll
        for (int half = 0; half < 2; half++) {
            int rloc = warp_m * 64 + mt * 16 + gid + half * 8;
            #pragma unroll
            for (int nt = 0; nt < 8; nt++) {
                int cloc = warp_n * 64 + nt * 8 + tq * 2;
                *(__half2*)&stage[rloc * K4STG + cloc] =
                    __floats2half2_rn(acc[mt][nt][half * 2], acc[mt][nt][half * 2 + 1]);
            }
        }
    }
    __syncthreads();
    #pragma unroll
    for (int t = 0; t < 16; t++) {
        int idx = tid + t * 256;          // 0..4095
        int row = idx >> 5, c32 = idx & 31;
        int gi = bm0 + row;
        int gn = bn0 + c32 * 8;
        int s  = gn >> 5;
        int d0 = gn & 31;
        uint4 v  = *(uint4*)&stage[row * K4STG + c32 * 8];
        uint4 g4 = *(const uint4*)&d_gh[((size_t)s * DN + gi) * DHC + h * DCH + d0];
        __half2* vh = (__half2*)&v;
        const __half2* gh = (const __half2*)&g4;
        #pragma unroll
        for (int q = 0; q < 4; q++) vh[q] = __hmul2(vh[q], gh[q]);
        *(uint4*)&d_oh[((size_t)gi * DS + s) * DHC + h * DCH + d0] = v;
    }
}

// ---------------------------------------------------------------------------
// K5 v2 (fp16 mma): out[128 x 64] = go[128 x 256] @ WoT[256 x 64]
// A-stage is pure contiguous uint4 copies from the gated-o layout.
// ---------------------------------------------------------------------------
constexpr int K5ST = 72;
constexpr int K5_SMEM = (128 * K5ST + 64 * K5ST) * 2;

__global__ void k5_out_fp16(float* __restrict__ out) {
    extern __shared__ __half sm5h[];
    __half* As = sm5h;
    __half* Bs = As + 128 * K5ST;

    const int tid = threadIdx.x;
    const int gr0 = blockIdx.x * 128;
    const int ss = gr0 / DN;
    const int i0 = gr0 - ss * DN;

    const int lane = tid & 31;
    const int wid  = tid >> 5;
    const int warp_m = wid >> 1;
    const int warp_n = wid & 1;
    const int gid = lane >> 2;
    const int tq  = lane & 3;

    float acc[2][4][4];
    #pragma unroll
    for (int i = 0; i < 2; i++)
        #pragma unroll
        for (int j = 0; j < 4; j++)
            #pragma unroll
            for (int r = 0; r < 4; r++) acc[i][j][r] = 0.f;

    for (int ck0 = 0; ck0 < DHC; ck0 += 64) {
        #pragma unroll
        for (int t = 0; t < 2; t++) {
            int idx = tid + t * 256;
            int n = idx >> 3, c8 = (idx & 7) * 8;
            *(uint4*)&Bs[n * K5ST + c8] = *(const uint4*)&d_woh[n * DHC + ck0 + c8];
        }
        // A-stage: contiguous uint4 copies of gated o rows
        #pragma unroll
        for (int t = 0; t < 4; t++) {
            int idx = tid + t * 256;     // 0..1023
            int r = idx >> 3, q = idx & 7;
            *(uint4*)&As[r * K5ST + q * 8] =
                *(const uint4*)&d_oh[((size_t)(i0 + r) * DS + ss) * DHC + ck0 + q * 8];
        }
        __syncthreads();

        #pragma unroll
        for (int k16 = 0; k16 < 4; k16++) {
            uint32_t af[2][4], bf[4][2];
            #pragma unroll
            for (int mt = 0; mt < 2; mt++) {
                int row = warp_m * 32 + mt * 16 + gid;
                af[mt][0] = *(const uint32_t*)&As[row * K5ST + k16 * 16 + tq * 2];
                af[mt][1] = *(const uint32_t*)&As[(row + 8) * K5ST + k16 * 16 + tq * 2];
                af[mt][2] = *(const uint32_t*)&As[row * K5ST + k16 * 16 + tq * 2 + 8];
                af[mt][3] = *(const uint32_t*)&As[(row + 8) * K5ST + k16 * 16 + tq * 2 + 8];
            }
            #pragma unroll
            for (int nt = 0; nt < 4; nt++) {
                int col = warp_n * 32 + nt * 8 + gid;
                bf[nt][0] = *(const uint32_t*)&Bs[col * K5ST + k16 * 16 + tq * 2];
                bf[nt][1] = *(const uint32_t*)&Bs[col * K5ST + k16 * 16 + tq * 2 + 8];
            }
            #pragma unroll
            for (int mt = 0; mt < 2; mt++)
                #pragma unroll
                for (int nt = 0; nt < 4; nt++)
                    MMA_F16(acc[mt][nt], af[mt], bf[nt]);
        }
        __syncthreads();
    }

    #pragma unroll
    for (int mt = 0; mt < 2; mt++) {
        #pragma unroll
        for (int nt = 0; nt < 4; nt++) {
            int row = gr0 + warp_m * 32 + mt * 16 + gid;
            int col = warp_n * 32 + nt * 8 + tq * 2;
            *(float2*)&out[(size_t)row * DCM + col] =
                make_float2(acc[mt][nt][0], acc[mt][nt][1]);
            *(float2*)&out[(size_t)(row + 8) * DCM + col] =
                make_float2(acc[mt][nt][2], acc[mt][nt][3]);
        }
    }
}

// ---------------------------------------------------------------------------
extern "C" void kernel_launch(void* const* d_in, const int* in_sizes, int n_in,
                              void* d_out, int out_size) {
    const float* m    = (const float*)d_in[0];
    const float* z    = (const float*)d_in[1];
    const int*   mask = (const int*)d_in[2];
    const float* nmw  = (const float*)d_in[3];
    const float* nmb  = (const float*)d_in[4];
    const float* nzw  = (const float*)d_in[5];
    const float* nzb  = (const float*)d_in[6];
    const float* Wm   = (const float*)d_in[7];
    const float* Wg   = (const float*)d_in[8];
    const float* Wz   = (const float*)d_in[9];
    const float* Wo   = (const float*)d_in[10];
    float* out = (float*)d_out;

    cudaFuncSetAttribute(k1_ln_vg_v3,     cudaFuncAttributeMaxDynamicSharedMemorySize, K1_SMEM);
    cudaFuncSetAttribute(k4_gemm_fp16_v8, cudaFuncAttributeMaxDynamicSharedMemorySize, K4_SMEM);
    cudaFuncSetAttribute(k5_out_fp16,     cudaFuncAttributeMaxDynamicSharedMemorySize, K5_SMEM);

    k0_convert_w<<<64, 256>>>(Wm, Wg, Wo);
    k1_ln_vg_v3<<<DSN / 128, 256, K1_SMEM>>>(m, nmw, nmb);
    k2_ln_bias_v2<<<DNN / 32, 256>>>(z, mask, nzw, nzb, Wz);
    k3_softmax<<<DH * DN, 256>>>();
    dim3 g4(DCOL / 256, DN / 128, DH);
    k4_gemm_fp16_v8<<<g4, 256, K4_SMEM>>>();
    k5_out_fp16<<<DSN / 128, 256, K5_SMEM>>>(out);
}